// round 13
// baseline (speedup 1.0000x reference)
#include <cuda_runtime.h>
#include <math.h>

#define TT 16
#define NN 128
#define FF 128
#define TN (TT*NN)
#define SEG (TT*NN*FF)

// ---- scratch (__device__ globals; no allocation allowed) ----
__device__ float g_aggr[4*SEG];       // 4 j-quarter partial aggregates
__device__ float g_y[SEG];
__device__ float g_node1[SEG];
__device__ float g_node2[SEG];
__device__ float g_stats[4*FF];       // [sum0(128), sumsq0(128), sum1, sumsq1]

__device__ __forceinline__ float tanh_fast(float x) {
    float y; asm("tanh.approx.f32 %0, %1;" : "=f"(y) : "f"(x)); return y;
}
__device__ __forceinline__ float lrelu(float v) { return v >= 0.0f ? v : 0.01f * v; }
__device__ __forceinline__ float dot4(float4 a, float4 b, float acc) {
    return fmaf(a.x, b.x, fmaf(a.y, b.y, fmaf(a.z, b.z, fmaf(a.w, b.w, acc))));
}

// ---- sim_cal (+ optional fused BN-apply + node write-back) ----
// grid=(64 tiles, T), 256 threads; 16x16 output tile per block, 1 output/thread.
// stats==nullptr: src is node feats, staged directly, no write-back.
// stats!=nullptr: src is pre-BN y; BN+lrelu applied during staging; diagonal
//                 tiles (nt==mt) write normalized rows to xout (each exactly once).
__global__ void __launch_bounds__(256) k_simcal(
        const float* __restrict__ src, const float* __restrict__ stats,
        const float* __restrict__ gamma, const float* __restrict__ beta,
        float* __restrict__ xout, float* __restrict__ out) {
    __shared__ float4 As[16*33], Bs[16*33];
    __shared__ float nA[16], nB[16];
    __shared__ float4 sc4[32], sh4[32];
    int t = blockIdx.y;
    int nt = blockIdx.x >> 3, mt = blockIdx.x & 7;
    int tid = threadIdx.x;
    bool bn = (stats != nullptr);
    if (bn && tid < 32) {
        const float inv = 1.0f / (float)TN;
        float4 sm = ((const float4*)stats)[tid];
        float4 sq = ((const float4*)(stats + FF))[tid];
        float4 gv = ((const float4*)gamma)[tid];
        float4 bv = ((const float4*)beta)[tid];
        float4 sc, sh;
        float mu = sm.x * inv; sc.x = rsqrtf(fmaf(-mu, mu, sq.x * inv) + 1e-5f) * gv.x; sh.x = fmaf(-mu, sc.x, bv.x);
        mu = sm.y * inv;       sc.y = rsqrtf(fmaf(-mu, mu, sq.y * inv) + 1e-5f) * gv.y; sh.y = fmaf(-mu, sc.y, bv.y);
        mu = sm.z * inv;       sc.z = rsqrtf(fmaf(-mu, mu, sq.z * inv) + 1e-5f) * gv.z; sh.z = fmaf(-mu, sc.z, bv.z);
        mu = sm.w * inv;       sc.w = rsqrtf(fmaf(-mu, mu, sq.w * inv) + 1e-5f) * gv.w; sh.w = fmaf(-mu, sc.w, bv.w);
        sc4[tid] = sc; sh4[tid] = sh;
    }
    if (bn) __syncthreads();
    // stage A (16 rows of nt-block) and B (16 rows of mt-block): 2 float4/thread each
    const float4* xa = (const float4*)(src + (t * NN + nt * 16) * FF);
    const float4* xb = (const float4*)(src + (t * NN + mt * 16) * FF);
#pragma unroll
    for (int i = 0; i < 2; ++i) {
        int idx = tid + i * 256;
        int r = idx >> 5, k = idx & 31;
        float4 a = xa[idx], b = xb[idx];
        if (bn) {
            float4 sc = sc4[k], sh = sh4[k];
            a.x = lrelu(fmaf(a.x, sc.x, sh.x)); a.y = lrelu(fmaf(a.y, sc.y, sh.y));
            a.z = lrelu(fmaf(a.z, sc.z, sh.z)); a.w = lrelu(fmaf(a.w, sc.w, sh.w));
            b.x = lrelu(fmaf(b.x, sc.x, sh.x)); b.y = lrelu(fmaf(b.y, sc.y, sh.y));
            b.z = lrelu(fmaf(b.z, sc.z, sh.z)); b.w = lrelu(fmaf(b.w, sc.w, sh.w));
        }
        As[r * 33 + k] = a;
        Bs[r * 33 + k] = b;
    }
    __syncthreads();
    // one warp computes the 32 row norms while the rest start the gram loop
    if (tid < 32) {
        int r = tid & 15;
        const float4* s4 = (tid < 16) ? As : Bs;
        float s = 0.f;
#pragma unroll 8
        for (int k = 0; k < 32; ++k) { float4 v = s4[r * 33 + k]; s = dot4(v, v, s); }
        if (tid < 16) nA[r] = sqrtf(s); else nB[r] = sqrtf(s);
    }
    int ra = tid >> 4, cb = tid & 15;   // row ra, col cb (adjacent lanes -> contiguous m)
    float acc = 0.f;
#pragma unroll 8
    for (int k = 0; k < 32; ++k)
        acc = dot4(As[ra * 33 + k], Bs[cb * 33 + k], acc);
    __syncthreads();   // norms visible
    int n = nt * 16 + ra;
    int m = mt * 16 + cb;
    float sim = __fdividef(acc, nA[ra] * nB[cb] + 1e-6f);
    float v0 = fminf(fmaxf(sim, 0.0f), 1.0f);
    float v1 = fminf(fmaxf(1.0f - sim, 0.0f), 1.0f);
    long ob0 = (long)(t * 2 + 0) * NN * NN;
    long ob1 = (long)(t * 2 + 1) * NN * NN;
    out[ob0 + n * NN + m] = v0;
    out[ob1 + n * NN + m] = v1;
    // diagonal tiles write the BN'd rows back (each 16-row block exactly once)
    if (bn && nt == mt) {
        float4* xo = (float4*)(xout + (t * NN + nt * 16) * FF);
#pragma unroll
        for (int i = 0; i < 2; ++i) {
            int idx = tid + i * 256;
            int r = idx >> 5, k = idx & 31;
            xo[idx] = As[r * 33 + k];
        }
    }
}

// ---- layer-0 edge update + partial aggregation over a 32-j quarter ----
// grid (32, T, 4), block 128: 4 i-rows per block, z selects j-quarter
__global__ void __launch_bounds__(128) k_edge0(
        const float* __restrict__ node, const float* __restrict__ edge,
        const float* __restrict__ ew, const float* __restrict__ eb,
        float* __restrict__ stats) {
    int z = blockIdx.z;
    if (z == 0 && blockIdx.x == 0 && blockIdx.y == 0) {
        stats[threadIdx.x] = 0.0f; stats[threadIdx.x + 128] = 0.0f;
    }
    int t = blockIdx.y;
    int lane = threadIdx.x & 31, w = threadIdx.x >> 5;
    int i = blockIdx.x * 4 + w;
    int j0 = z * 32;
    float w0 = ew[0], w1 = ew[1], w2 = ew[2], b = eb[0];
    const float4* x4 = (const float4*)(node + t * NN * FF);
    float4 xi = x4[i * 32 + lane];
    float cx = fmaf(w0 + w1, xi.x, b), cy = fmaf(w0 + w1, xi.y, b);
    float cz = fmaf(w0 + w1, xi.z, b), cw_ = fmaf(w0 + w1, xi.w, b);
    const float4* e4 = (const float4*)(edge + ((size_t)(t * NN + i) * NN) * FF);
    float ax = 0.f, ay = 0.f, az = 0.f, aw = 0.f;
#pragma unroll 8
    for (int jj = 0; jj < 32; ++jj) {
        int j = j0 + jj;
        float4 e = __ldcs(&e4[j * 32 + lane]);
        float4 xj = x4[j * 32 + lane];
        ax += tanh_fast(fmaf(w2, e.x, fmaf(-w1, xj.x, cx)));
        ay += tanh_fast(fmaf(w2, e.y, fmaf(-w1, xj.y, cy)));
        az += tanh_fast(fmaf(w2, e.z, fmaf(-w1, xj.z, cz)));
        aw += tanh_fast(fmaf(w2, e.w, fmaf(-w1, xj.w, cw_)));
    }
    if ((i >> 5) == z) {   // subtract diagonal if i falls in this quarter
        float4 eii = e4[i * 32 + lane];
        ax -= tanh_fast(fmaf(w2, eii.x, fmaf(-w1, xi.x, cx)));
        ay -= tanh_fast(fmaf(w2, eii.y, fmaf(-w1, xi.y, cy)));
        az -= tanh_fast(fmaf(w2, eii.z, fmaf(-w1, xi.z, cz)));
        aw -= tanh_fast(fmaf(w2, eii.w, fmaf(-w1, xi.w, cw_)));
    }
    float4 acc; acc.x = ax; acc.y = ay; acc.z = az; acc.w = aw;
    ((float4*)(g_aggr + z * SEG + (t * NN + i) * FF))[lane] = acc;
}

// ---- layer-1: recompute e0 on the fly, chain layer-1 tanh, partial-aggregate ----
__global__ void __launch_bounds__(128) k_edge1(
        const float* __restrict__ node0, const float* __restrict__ node1,
        const float* __restrict__ edge,
        const float* __restrict__ ew, const float* __restrict__ eb,
        float* __restrict__ stats) {
    int z = blockIdx.z;
    if (z == 0 && blockIdx.x == 0 && blockIdx.y == 0) {
        stats[threadIdx.x] = 0.0f; stats[threadIdx.x + 128] = 0.0f;
    }
    int t = blockIdx.y;
    int lane = threadIdx.x & 31, w = threadIdx.x >> 5;
    int i = blockIdx.x * 4 + w;
    int j0 = z * 32;
    float w00 = ew[0], w01 = ew[1], w02 = ew[2], b0 = eb[0];
    float w10 = ew[3], w11 = ew[4], w12 = ew[5], b1 = eb[1];
    const float4* x04 = (const float4*)(node0 + t * NN * FF);
    const float4* x14 = (const float4*)(node1 + t * NN * FF);
    float4 xi0 = x04[i * 32 + lane];
    float4 xi1 = x14[i * 32 + lane];
    float c0x = fmaf(w00 + w01, xi0.x, b0), c0y = fmaf(w00 + w01, xi0.y, b0);
    float c0z = fmaf(w00 + w01, xi0.z, b0), c0w = fmaf(w00 + w01, xi0.w, b0);
    float c1x = fmaf(w10 + w11, xi1.x, b1), c1y = fmaf(w10 + w11, xi1.y, b1);
    float c1z = fmaf(w10 + w11, xi1.z, b1), c1w = fmaf(w10 + w11, xi1.w, b1);
    const float4* e4 = (const float4*)(edge + ((size_t)(t * NN + i) * NN) * FF);
    float ax = 0.f, ay = 0.f, az = 0.f, aw = 0.f;
#pragma unroll 4
    for (int jj = 0; jj < 32; ++jj) {
        int j = j0 + jj;
        float4 e  = __ldcs(&e4[j * 32 + lane]);
        float4 x0 = x04[j * 32 + lane];
        float4 x1 = x14[j * 32 + lane];
        float e0x = tanh_fast(fmaf(w02, e.x, fmaf(-w01, x0.x, c0x)));
        float e0y = tanh_fast(fmaf(w02, e.y, fmaf(-w01, x0.y, c0y)));
        float e0z = tanh_fast(fmaf(w02, e.z, fmaf(-w01, x0.z, c0z)));
        float e0w = tanh_fast(fmaf(w02, e.w, fmaf(-w01, x0.w, c0w)));
        ax += tanh_fast(fmaf(w12, e0x, fmaf(-w11, x1.x, c1x)));
        ay += tanh_fast(fmaf(w12, e0y, fmaf(-w11, x1.y, c1y)));
        az += tanh_fast(fmaf(w12, e0z, fmaf(-w11, x1.z, c1z)));
        aw += tanh_fast(fmaf(w12, e0w, fmaf(-w11, x1.w, c1w)));
    }
    if ((i >> 5) == z) {
        float4 e = e4[i * 32 + lane];
        float e0x = tanh_fast(fmaf(w02, e.x, fmaf(-w01, xi0.x, c0x)));
        float e0y = tanh_fast(fmaf(w02, e.y, fmaf(-w01, xi0.y, c0y)));
        float e0z = tanh_fast(fmaf(w02, e.z, fmaf(-w01, xi0.z, c0z)));
        float e0w = tanh_fast(fmaf(w02, e.w, fmaf(-w01, xi0.w, c0w)));
        ax -= tanh_fast(fmaf(w12, e0x, fmaf(-w11, xi1.x, c1x)));
        ay -= tanh_fast(fmaf(w12, e0y, fmaf(-w11, xi1.y, c1y)));
        az -= tanh_fast(fmaf(w12, e0z, fmaf(-w11, xi1.z, c1z)));
        aw -= tanh_fast(fmaf(w12, e0w, fmaf(-w11, xi1.w, c1w)));
    }
    float4 acc; acc.x = ax; acc.y = ay; acc.z = az; acc.w = aw;
    ((float4*)(g_aggr + z * SEG + (t * NN + i) * FF))[lane] = acc;
}

// ---- node GEMM (all-float4 mainloop) + fused BN-stat accumulation ----
// grid T*8 (16-row tiles), 256 threads; dyn smem: Ws4[128][33] + hs4[16][33]
__global__ void __launch_bounds__(256) k_gemm(
        const float* __restrict__ x, const float* __restrict__ cw,
        const float* __restrict__ W, float* __restrict__ y, float* __restrict__ stats) {
    extern __shared__ float4 sm4[];
    float4* Ws = sm4;               // [g][k], pitch 33 float4
    float4* hs = sm4 + 128 * 33;    // [r][k], pitch 33 float4
    float c0 = cw[0], c1 = cw[1];
    int t = blockIdx.x >> 3;
    int r0 = (blockIdx.x & 7) * 16;
    int tid = threadIdx.x;
    const float4* W4 = (const float4*)W;
#pragma unroll
    for (int i = 0; i < 16; ++i) {
        int idx = tid + i * 256;
        int g = idx >> 5, k = idx & 31;
        Ws[g * 33 + k] = W4[idx];
    }
    const float4* x4 = (const float4*)(x + (t * NN + r0) * FF);
    const float4* a4 = (const float4*)(g_aggr + 0 * SEG + (t * NN + r0) * FF);
    const float4* b4 = (const float4*)(g_aggr + 1 * SEG + (t * NN + r0) * FF);
    const float4* c4 = (const float4*)(g_aggr + 2 * SEG + (t * NN + r0) * FF);
    const float4* d4 = (const float4*)(g_aggr + 3 * SEG + (t * NN + r0) * FF);
#pragma unroll
    for (int i = 0; i < 2; ++i) {
        int idx = tid + i * 256;
        int r = idx >> 5, k = idx & 31;
        float4 xv = x4[idx], av = a4[idx], bv = b4[idx], cv = c4[idx], dv = d4[idx], h;
        h.x = lrelu(fmaf(c1, (av.x + bv.x) + (cv.x + dv.x), c0 * xv.x));
        h.y = lrelu(fmaf(c1, (av.y + bv.y) + (cv.y + dv.y), c0 * xv.y));
        h.z = lrelu(fmaf(c1, (av.z + bv.z) + (cv.z + dv.z), c0 * xv.z));
        h.w = lrelu(fmaf(c1, (av.w + bv.w) + (cv.w + dv.w), c0 * xv.w));
        hs[r * 33 + k] = h;
    }
    __syncthreads();
    int rt = tid & 7, gt = tid >> 3;   // rows {rt, rt+8}, g's gt*4..+3
    float acc[2][4] = { {0.f,0.f,0.f,0.f}, {0.f,0.f,0.f,0.f} };
#pragma unroll 4
    for (int k = 0; k < 32; ++k) {
        float4 a0 = hs[rt * 33 + k];
        float4 a1 = hs[(rt + 8) * 33 + k];
#pragma unroll
        for (int q = 0; q < 4; ++q) {
            float4 wv = Ws[(gt * 4 + q) * 33 + k];
            acc[0][q] = dot4(a0, wv, acc[0][q]);
            acc[1][q] = dot4(a1, wv, acc[1][q]);
        }
    }
    float4 v0; v0.x = acc[0][0]; v0.y = acc[0][1]; v0.z = acc[0][2]; v0.w = acc[0][3];
    float4 v1; v1.x = acc[1][0]; v1.y = acc[1][1]; v1.z = acc[1][2]; v1.w = acc[1][3];
    *(float4*)(y + (t * NN + r0 + rt) * FF + gt * 4) = v0;
    *(float4*)(y + (t * NN + r0 + rt + 8) * FF + gt * 4) = v1;
#pragma unroll
    for (int q = 0; q < 4; ++q) {
        float s  = acc[0][q] + acc[1][q];
        float ss = fmaf(acc[0][q], acc[0][q], acc[1][q] * acc[1][q]);
#pragma unroll
        for (int o = 4; o; o >>= 1) {
            s  += __shfl_down_sync(0xffffffffu, s,  o, 8);
            ss += __shfl_down_sync(0xffffffffu, ss, o, 8);
        }
        if (rt == 0) {
            int g = gt * 4 + q;
            atomicAdd(&stats[g], s);
            atomicAdd(&stats[FF + g], ss);
        }
    }
}

extern "C" void kernel_launch(void* const* d_in, const int* in_sizes, int n_in,
                              void* d_out, int out_size) {
    const float* node  = (const float*)d_in[0];
    const float* edge  = (const float*)d_in[1];
    const float* ew    = (const float*)d_in[2];   // [L,3]
    const float* ebv   = (const float*)d_in[3];   // [L]
    const float* cw    = (const float*)d_in[4];   // [L,2]
    const float* nw    = (const float*)d_in[5];   // [L,F,F]
    const float* gamma = (const float*)d_in[6];   // [L,F]
    const float* beta  = (const float*)d_in[7];   // [L,F]
    float* out = (float*)d_out;

    void *p1, *p2, *py, *ps;
    cudaGetSymbolAddress(&p1, g_node1);
    cudaGetSymbolAddress(&p2, g_node2);
    cudaGetSymbolAddress(&py, g_y);
    cudaGetSymbolAddress(&ps, g_stats);
    float* node1 = (float*)p1;
    float* node2 = (float*)p2;
    float* y     = (float*)py;
    float* st    = (float*)ps;

    size_t gemm_smem = (size_t)(128 * 33 + 16 * 33) * sizeof(float4);
    cudaFuncSetAttribute(k_gemm, cudaFuncAttributeMaxDynamicSharedMemorySize, (int)gemm_smem);

    const int OUTBLK = TT * 2 * NN * NN;

    // sim_cal on input features (no BN)
    k_simcal<<<dim3(64, TT), 256>>>(node, nullptr, nullptr, nullptr, nullptr, out);

    // ---- layer 0 ----
    k_edge0<<<dim3(32, TT, 4), 128>>>(node, edge, ew, ebv, st);
    k_gemm<<<TT * 8, 256, gemm_smem>>>(node, cw, nw, y, st);
    // BN-apply fused into simcal; diagonal tiles write node1
    k_simcal<<<dim3(64, TT), 256>>>(y, st, gamma, beta, node1, out + OUTBLK);

    // ---- layer 1 (recompute layer-0 edges on the fly) ----
    k_edge1<<<dim3(32, TT, 4), 128>>>(node, node1, edge, ew, ebv, st + 2 * FF);
    k_gemm<<<TT * 8, 256, gemm_smem>>>(node1, cw + 2, nw + FF * FF, y, st + 2 * FF);
    k_simcal<<<dim3(64, TT), 256>>>(y, st + 2 * FF, gamma + FF, beta + FF, node2,
                                    out + 2 * OUTBLK);
}

// round 14
// speedup vs baseline: 1.4552x; 1.4552x over previous
#include <cuda_runtime.h>
#include <math.h>

#define TT 16
#define NN 128
#define FF 128
#define TN (TT*NN)
#define SEG (TT*NN*FF)

// ---- scratch (__device__ globals; no allocation allowed) ----
__device__ float g_aggr[4*SEG];       // 4 j-quarter partial aggregates
__device__ float g_y[SEG];
__device__ float g_node1[SEG];
__device__ float g_node2[SEG];
__device__ float g_stats[4*FF];       // [sum0(128), sumsq0(128), sum1, sumsq1]

__device__ __forceinline__ float tanh_fast(float x) {
    float y; asm("tanh.approx.f32 %0, %1;" : "=f"(y) : "f"(x)); return y;
}
__device__ __forceinline__ float lrelu(float v) { return v >= 0.0f ? v : 0.01f * v; }
__device__ __forceinline__ float dot4(float4 a, float4 b, float acc) {
    return fmaf(a.x, b.x, fmaf(a.y, b.y, fmaf(a.z, b.z, fmaf(a.w, b.w, acc))));
}

// ---- sim_cal (+ optional fused BN-apply + node write-back) ----
// grid=(16 tiles, T), 256 threads; 32x32 output tile, 2x2 per thread.
// All 16 (nt,mt) tiles -> 256 blocks -> ~2 blocks/SM (4 warps/SMSP latency hiding).
// stats==nullptr: src is node feats, staged directly, no write-back.
// stats!=nullptr: src is pre-BN y; BN+lrelu applied during staging; diagonal
//                 tiles (nt==mt) write normalized rows to xout (each exactly once).
__global__ void __launch_bounds__(256) k_simcal(
        const float* __restrict__ src, const float* __restrict__ stats,
        const float* __restrict__ gamma, const float* __restrict__ beta,
        float* __restrict__ xout, float* __restrict__ out) {
    __shared__ float4 As[32*33], Bs[32*33];
    __shared__ float nA[32], nB[32];
    __shared__ float4 sc4[32], sh4[32];
    int t = blockIdx.y;
    int nt = blockIdx.x >> 2, mt = blockIdx.x & 3;
    int tid = threadIdx.x;
    bool bn = (stats != nullptr);
    if (bn && tid < 32) {
        const float inv = 1.0f / (float)TN;
        float4 sm = ((const float4*)stats)[tid];
        float4 sq = ((const float4*)(stats + FF))[tid];
        float4 gv = ((const float4*)gamma)[tid];
        float4 bv = ((const float4*)beta)[tid];
        float4 sc, sh;
        float mu = sm.x * inv; sc.x = rsqrtf(fmaf(-mu, mu, sq.x * inv) + 1e-5f) * gv.x; sh.x = fmaf(-mu, sc.x, bv.x);
        mu = sm.y * inv;       sc.y = rsqrtf(fmaf(-mu, mu, sq.y * inv) + 1e-5f) * gv.y; sh.y = fmaf(-mu, sc.y, bv.y);
        mu = sm.z * inv;       sc.z = rsqrtf(fmaf(-mu, mu, sq.z * inv) + 1e-5f) * gv.z; sh.z = fmaf(-mu, sc.z, bv.z);
        mu = sm.w * inv;       sc.w = rsqrtf(fmaf(-mu, mu, sq.w * inv) + 1e-5f) * gv.w; sh.w = fmaf(-mu, sc.w, bv.w);
        sc4[tid] = sc; sh4[tid] = sh;
    }
    if (bn) __syncthreads();
    const float4* xa = (const float4*)(src + (t * NN + nt * 32) * FF);
    const float4* xb = (const float4*)(src + (t * NN + mt * 32) * FF);
#pragma unroll
    for (int i = 0; i < 4; ++i) {
        int idx = tid + i * 256;
        int r = idx >> 5, k = idx & 31;
        float4 a = xa[idx], b = xb[idx];
        if (bn) {
            float4 sc = sc4[k], sh = sh4[k];
            a.x = lrelu(fmaf(a.x, sc.x, sh.x)); a.y = lrelu(fmaf(a.y, sc.y, sh.y));
            a.z = lrelu(fmaf(a.z, sc.z, sh.z)); a.w = lrelu(fmaf(a.w, sc.w, sh.w));
            b.x = lrelu(fmaf(b.x, sc.x, sh.x)); b.y = lrelu(fmaf(b.y, sc.y, sh.y));
            b.z = lrelu(fmaf(b.z, sc.z, sh.z)); b.w = lrelu(fmaf(b.w, sc.w, sh.w));
        }
        As[r * 33 + k] = a;
        Bs[r * 33 + k] = b;
    }
    __syncthreads();
    // two warps compute the row norms while the rest run the gram loop
    if (tid < 64) {
        int r = tid & 31;
        const float4* s4 = (tid < 32) ? As : Bs;
        float s = 0.f;
#pragma unroll 8
        for (int k = 0; k < 32; ++k) { float4 v = s4[r * 33 + k]; s = dot4(v, v, s); }
        if (tid < 32) nA[r] = sqrtf(s); else nB[r] = sqrtf(s);
    }
    int ra = tid & 15, cb = tid >> 4;     // rows {ra, ra+16}, cols {cb, cb+16}
    float a00 = 0.f, a01 = 0.f, a10 = 0.f, a11 = 0.f;
#pragma unroll 8
    for (int k = 0; k < 32; ++k) {
        float4 r0 = As[ra * 33 + k], r1 = As[(ra + 16) * 33 + k];
        float4 q0 = Bs[cb * 33 + k], q1 = Bs[(cb + 16) * 33 + k];
        a00 = dot4(r0, q0, a00); a01 = dot4(r0, q1, a01);
        a10 = dot4(r1, q0, a10); a11 = dot4(r1, q1, a11);
    }
    __syncthreads();   // norms visible
    float na[2] = { nA[ra], nA[ra + 16] };
    float nb[2] = { nB[cb], nB[cb + 16] };
    float acc[2][2] = { {a00, a01}, {a10, a11} };
    long ob0 = (long)(t * 2 + 0) * NN * NN;
    long ob1 = (long)(t * 2 + 1) * NN * NN;
#pragma unroll
    for (int k = 0; k < 2; ++k) {
#pragma unroll
        for (int q = 0; q < 2; ++q) {
            int n = nt * 32 + ra + k * 16;
            int m = mt * 32 + cb + q * 16;
            float sim = __fdividef(acc[k][q], na[k] * nb[q] + 1e-6f);
            float v0 = fminf(fmaxf(sim, 0.0f), 1.0f);
            float v1 = fminf(fmaxf(1.0f - sim, 0.0f), 1.0f);
            out[ob0 + n * NN + m] = v0;
            out[ob1 + n * NN + m] = v1;
        }
    }
    // diagonal tiles write the BN'd rows back (each 32-row block exactly once)
    if (bn && nt == mt) {
        float4* xo = (float4*)(xout + (t * NN + nt * 32) * FF);
#pragma unroll
        for (int i = 0; i < 4; ++i) {
            int idx = tid + i * 256;
            int r = idx >> 5, k = idx & 31;
            xo[idx] = As[r * 33 + k];
        }
    }
}

// ---- layer-0 edge update + partial aggregation over a 32-j quarter ----
// grid (32, T, 4), block 128: 4 i-rows per block, z selects j-quarter
__global__ void __launch_bounds__(128) k_edge0(
        const float* __restrict__ node, const float* __restrict__ edge,
        const float* __restrict__ ew, const float* __restrict__ eb,
        float* __restrict__ stats) {
    int z = blockIdx.z;
    if (z == 0 && blockIdx.x == 0 && blockIdx.y == 0) {
        stats[threadIdx.x] = 0.0f; stats[threadIdx.x + 128] = 0.0f;
    }
    int t = blockIdx.y;
    int lane = threadIdx.x & 31, w = threadIdx.x >> 5;
    int i = blockIdx.x * 4 + w;
    int j0 = z * 32;
    float w0 = ew[0], w1 = ew[1], w2 = ew[2], b = eb[0];
    const float4* x4 = (const float4*)(node + t * NN * FF);
    float4 xi = x4[i * 32 + lane];
    float cx = fmaf(w0 + w1, xi.x, b), cy = fmaf(w0 + w1, xi.y, b);
    float cz = fmaf(w0 + w1, xi.z, b), cw_ = fmaf(w0 + w1, xi.w, b);
    const float4* e4 = (const float4*)(edge + ((size_t)(t * NN + i) * NN) * FF);
    float ax = 0.f, ay = 0.f, az = 0.f, aw = 0.f;
#pragma unroll 8
    for (int jj = 0; jj < 32; ++jj) {
        int j = j0 + jj;
        float4 e = __ldcs(&e4[j * 32 + lane]);
        float4 xj = x4[j * 32 + lane];
        ax += tanh_fast(fmaf(w2, e.x, fmaf(-w1, xj.x, cx)));
        ay += tanh_fast(fmaf(w2, e.y, fmaf(-w1, xj.y, cy)));
        az += tanh_fast(fmaf(w2, e.z, fmaf(-w1, xj.z, cz)));
        aw += tanh_fast(fmaf(w2, e.w, fmaf(-w1, xj.w, cw_)));
    }
    if ((i >> 5) == z) {   // subtract diagonal if i falls in this quarter
        float4 eii = e4[i * 32 + lane];
        ax -= tanh_fast(fmaf(w2, eii.x, fmaf(-w1, xi.x, cx)));
        ay -= tanh_fast(fmaf(w2, eii.y, fmaf(-w1, xi.y, cy)));
        az -= tanh_fast(fmaf(w2, eii.z, fmaf(-w1, xi.z, cz)));
        aw -= tanh_fast(fmaf(w2, eii.w, fmaf(-w1, xi.w, cw_)));
    }
    float4 acc; acc.x = ax; acc.y = ay; acc.z = az; acc.w = aw;
    ((float4*)(g_aggr + z * SEG + (t * NN + i) * FF))[lane] = acc;
}

// ---- layer-1: recompute e0 on the fly, chain layer-1 tanh, partial-aggregate ----
__global__ void __launch_bounds__(128) k_edge1(
        const float* __restrict__ node0, const float* __restrict__ node1,
        const float* __restrict__ edge,
        const float* __restrict__ ew, const float* __restrict__ eb,
        float* __restrict__ stats) {
    int z = blockIdx.z;
    if (z == 0 && blockIdx.x == 0 && blockIdx.y == 0) {
        stats[threadIdx.x] = 0.0f; stats[threadIdx.x + 128] = 0.0f;
    }
    int t = blockIdx.y;
    int lane = threadIdx.x & 31, w = threadIdx.x >> 5;
    int i = blockIdx.x * 4 + w;
    int j0 = z * 32;
    float w00 = ew[0], w01 = ew[1], w02 = ew[2], b0 = eb[0];
    float w10 = ew[3], w11 = ew[4], w12 = ew[5], b1 = eb[1];
    const float4* x04 = (const float4*)(node0 + t * NN * FF);
    const float4* x14 = (const float4*)(node1 + t * NN * FF);
    float4 xi0 = x04[i * 32 + lane];
    float4 xi1 = x14[i * 32 + lane];
    float c0x = fmaf(w00 + w01, xi0.x, b0), c0y = fmaf(w00 + w01, xi0.y, b0);
    float c0z = fmaf(w00 + w01, xi0.z, b0), c0w = fmaf(w00 + w01, xi0.w, b0);
    float c1x = fmaf(w10 + w11, xi1.x, b1), c1y = fmaf(w10 + w11, xi1.y, b1);
    float c1z = fmaf(w10 + w11, xi1.z, b1), c1w = fmaf(w10 + w11, xi1.w, b1);
    const float4* e4 = (const float4*)(edge + ((size_t)(t * NN + i) * NN) * FF);
    float ax = 0.f, ay = 0.f, az = 0.f, aw = 0.f;
#pragma unroll 4
    for (int jj = 0; jj < 32; ++jj) {
        int j = j0 + jj;
        float4 e  = __ldcs(&e4[j * 32 + lane]);
        float4 x0 = x04[j * 32 + lane];
        float4 x1 = x14[j * 32 + lane];
        float e0x = tanh_fast(fmaf(w02, e.x, fmaf(-w01, x0.x, c0x)));
        float e0y = tanh_fast(fmaf(w02, e.y, fmaf(-w01, x0.y, c0y)));
        float e0z = tanh_fast(fmaf(w02, e.z, fmaf(-w01, x0.z, c0z)));
        float e0w = tanh_fast(fmaf(w02, e.w, fmaf(-w01, x0.w, c0w)));
        ax += tanh_fast(fmaf(w12, e0x, fmaf(-w11, x1.x, c1x)));
        ay += tanh_fast(fmaf(w12, e0y, fmaf(-w11, x1.y, c1y)));
        az += tanh_fast(fmaf(w12, e0z, fmaf(-w11, x1.z, c1z)));
        aw += tanh_fast(fmaf(w12, e0w, fmaf(-w11, x1.w, c1w)));
    }
    if ((i >> 5) == z) {
        float4 e = e4[i * 32 + lane];
        float e0x = tanh_fast(fmaf(w02, e.x, fmaf(-w01, xi0.x, c0x)));
        float e0y = tanh_fast(fmaf(w02, e.y, fmaf(-w01, xi0.y, c0y)));
        float e0z = tanh_fast(fmaf(w02, e.z, fmaf(-w01, xi0.z, c0z)));
        float e0w = tanh_fast(fmaf(w02, e.w, fmaf(-w01, xi0.w, c0w)));
        ax -= tanh_fast(fmaf(w12, e0x, fmaf(-w11, xi1.x, c1x)));
        ay -= tanh_fast(fmaf(w12, e0y, fmaf(-w11, xi1.y, c1y)));
        az -= tanh_fast(fmaf(w12, e0z, fmaf(-w11, xi1.z, c1z)));
        aw -= tanh_fast(fmaf(w12, e0w, fmaf(-w11, xi1.w, c1w)));
    }
    float4 acc; acc.x = ax; acc.y = ay; acc.z = az; acc.w = aw;
    ((float4*)(g_aggr + z * SEG + (t * NN + i) * FF))[lane] = acc;
}

// ---- node GEMM (all-float4 mainloop) + fused BN-stat accumulation ----
// grid T*8 (16-row tiles), 256 threads; dyn smem: Ws4[128][33] + hs4[16][33]
__global__ void __launch_bounds__(256) k_gemm(
        const float* __restrict__ x, const float* __restrict__ cw,
        const float* __restrict__ W, float* __restrict__ y, float* __restrict__ stats) {
    extern __shared__ float4 sm4[];
    float4* Ws = sm4;               // [g][k], pitch 33 float4
    float4* hs = sm4 + 128 * 33;    // [r][k], pitch 33 float4
    float c0 = cw[0], c1 = cw[1];
    int t = blockIdx.x >> 3;
    int r0 = (blockIdx.x & 7) * 16;
    int tid = threadIdx.x;
    const float4* W4 = (const float4*)W;
#pragma unroll
    for (int i = 0; i < 16; ++i) {
        int idx = tid + i * 256;
        int g = idx >> 5, k = idx & 31;
        Ws[g * 33 + k] = W4[idx];
    }
    const float4* x4 = (const float4*)(x + (t * NN + r0) * FF);
    const float4* a4 = (const float4*)(g_aggr + 0 * SEG + (t * NN + r0) * FF);
    const float4* b4 = (const float4*)(g_aggr + 1 * SEG + (t * NN + r0) * FF);
    const float4* c4 = (const float4*)(g_aggr + 2 * SEG + (t * NN + r0) * FF);
    const float4* d4 = (const float4*)(g_aggr + 3 * SEG + (t * NN + r0) * FF);
#pragma unroll
    for (int i = 0; i < 2; ++i) {
        int idx = tid + i * 256;
        int r = idx >> 5, k = idx & 31;
        float4 xv = x4[idx], av = a4[idx], bv = b4[idx], cv = c4[idx], dv = d4[idx], h;
        h.x = lrelu(fmaf(c1, (av.x + bv.x) + (cv.x + dv.x), c0 * xv.x));
        h.y = lrelu(fmaf(c1, (av.y + bv.y) + (cv.y + dv.y), c0 * xv.y));
        h.z = lrelu(fmaf(c1, (av.z + bv.z) + (cv.z + dv.z), c0 * xv.z));
        h.w = lrelu(fmaf(c1, (av.w + bv.w) + (cv.w + dv.w), c0 * xv.w));
        hs[r * 33 + k] = h;
    }
    __syncthreads();
    int rt = tid & 7, gt = tid >> 3;   // rows {rt, rt+8}, g's gt*4..+3
    float acc[2][4] = { {0.f,0.f,0.f,0.f}, {0.f,0.f,0.f,0.f} };
#pragma unroll 4
    for (int k = 0; k < 32; ++k) {
        float4 a0 = hs[rt * 33 + k];
        float4 a1 = hs[(rt + 8) * 33 + k];
#pragma unroll
        for (int q = 0; q < 4; ++q) {
            float4 wv = Ws[(gt * 4 + q) * 33 + k];
            acc[0][q] = dot4(a0, wv, acc[0][q]);
            acc[1][q] = dot4(a1, wv, acc[1][q]);
        }
    }
    float4 v0; v0.x = acc[0][0]; v0.y = acc[0][1]; v0.z = acc[0][2]; v0.w = acc[0][3];
    float4 v1; v1.x = acc[1][0]; v1.y = acc[1][1]; v1.z = acc[1][2]; v1.w = acc[1][3];
    *(float4*)(y + (t * NN + r0 + rt) * FF + gt * 4) = v0;
    *(float4*)(y + (t * NN + r0 + rt + 8) * FF + gt * 4) = v1;
#pragma unroll
    for (int q = 0; q < 4; ++q) {
        float s  = acc[0][q] + acc[1][q];
        float ss = fmaf(acc[0][q], acc[0][q], acc[1][q] * acc[1][q]);
#pragma unroll
        for (int o = 4; o; o >>= 1) {
            s  += __shfl_down_sync(0xffffffffu, s,  o, 8);
            ss += __shfl_down_sync(0xffffffffu, ss, o, 8);
        }
        if (rt == 0) {
            int g = gt * 4 + q;
            atomicAdd(&stats[g], s);
            atomicAdd(&stats[FF + g], ss);
        }
    }
}

extern "C" void kernel_launch(void* const* d_in, const int* in_sizes, int n_in,
                              void* d_out, int out_size) {
    const float* node  = (const float*)d_in[0];
    const float* edge  = (const float*)d_in[1];
    const float* ew    = (const float*)d_in[2];   // [L,3]
    const float* ebv   = (const float*)d_in[3];   // [L]
    const float* cw    = (const float*)d_in[4];   // [L,2]
    const float* nw    = (const float*)d_in[5];   // [L,F,F]
    const float* gamma = (const float*)d_in[6];   // [L,F]
    const float* beta  = (const float*)d_in[7];   // [L,F]
    float* out = (float*)d_out;

    void *p1, *p2, *py, *ps;
    cudaGetSymbolAddress(&p1, g_node1);
    cudaGetSymbolAddress(&p2, g_node2);
    cudaGetSymbolAddress(&py, g_y);
    cudaGetSymbolAddress(&ps, g_stats);
    float* node1 = (float*)p1;
    float* node2 = (float*)p2;
    float* y     = (float*)py;
    float* st    = (float*)ps;

    size_t gemm_smem = (size_t)(128 * 33 + 16 * 33) * sizeof(float4);
    cudaFuncSetAttribute(k_gemm, cudaFuncAttributeMaxDynamicSharedMemorySize, (int)gemm_smem);

    const int OUTBLK = TT * 2 * NN * NN;

    // sim_cal on input features (no BN)
    k_simcal<<<dim3(16, TT), 256>>>(node, nullptr, nullptr, nullptr, nullptr, out);

    // ---- layer 0 ----
    k_edge0<<<dim3(32, TT, 4), 128>>>(node, edge, ew, ebv, st);
    k_gemm<<<TT * 8, 256, gemm_smem>>>(node, cw, nw, y, st);
    // BN-apply fused into simcal; diagonal tiles write node1
    k_simcal<<<dim3(16, TT), 256>>>(y, st, gamma, beta, node1, out + OUTBLK);

    // ---- layer 1 (recompute layer-0 edges on the fly) ----
    k_edge1<<<dim3(32, TT, 4), 128>>>(node, node1, edge, ew, ebv, st + 2 * FF);
    k_gemm<<<TT * 8, 256, gemm_smem>>>(node1, cw + 2, nw + FF * FF, y, st + 2 * FF);
    k_simcal<<<dim3(16, TT), 256>>>(y, st + 2 * FF, gamma + FF, beta + FF, node2,
                                    out + 2 * OUTBLK);
}

// round 15
// speedup vs baseline: 1.4983x; 1.0297x over previous
#include <cuda_runtime.h>
#include <math.h>

#define TT 16
#define NN 128
#define FF 128
#define TN (TT*NN)
#define SEG (TT*NN*FF)

// ---- scratch (__device__ globals; no allocation allowed) ----
__device__ float g_aggr[4*SEG];       // 4 j-quarter partial aggregates
__device__ float g_y[SEG];
__device__ float g_node1[SEG];
__device__ float g_node2[SEG];
__device__ float g_stats[4*FF];       // [sum0(128), sumsq0(128), sum1, sumsq1]

__device__ __forceinline__ float tanh_fast(float x) {
    float y; asm("tanh.approx.f32 %0, %1;" : "=f"(y) : "f"(x)); return y;
}
__device__ __forceinline__ float lrelu(float v) { return v >= 0.0f ? v : 0.01f * v; }
__device__ __forceinline__ void fma4(float4 a, float4 b, float4& s) {
    s.x = fmaf(a.x, b.x, s.x); s.y = fmaf(a.y, b.y, s.y);
    s.z = fmaf(a.z, b.z, s.z); s.w = fmaf(a.w, b.w, s.w);
}
__device__ __forceinline__ float hsum4(float4 s) { return (s.x + s.y) + (s.z + s.w); }

// ---- sim_cal body: 32x32 tile, 2x2/thread, 16 independent FMA chains ----
// BN=false: src is node feats.  BN=true: src is pre-BN y; BN+lrelu during staging;
// diagonal tiles (nt==mt) write normalized rows to xout.
template<bool BN>
__device__ __forceinline__ void simcal_body(
        const float* __restrict__ src, const float* __restrict__ stats,
        const float* __restrict__ gamma, const float* __restrict__ beta,
        float* __restrict__ xout, float* __restrict__ out,
        int t, int tilex, int tid) {
    __shared__ float4 As[32*33], Bs[32*33];
    __shared__ float nA[32], nB[32];
    __shared__ float4 sc4[32], sh4[32];
    int nt = tilex >> 2, mt = tilex & 3;
    if (BN) {
        if (tid < 32) {
            const float inv = 1.0f / (float)TN;
            float4 sm = ((const float4*)stats)[tid];
            float4 sq = ((const float4*)(stats + FF))[tid];
            float4 gv = ((const float4*)gamma)[tid];
            float4 bv = ((const float4*)beta)[tid];
            float4 sc, sh;
            float mu = sm.x * inv; sc.x = rsqrtf(fmaf(-mu, mu, sq.x * inv) + 1e-5f) * gv.x; sh.x = fmaf(-mu, sc.x, bv.x);
            mu = sm.y * inv;       sc.y = rsqrtf(fmaf(-mu, mu, sq.y * inv) + 1e-5f) * gv.y; sh.y = fmaf(-mu, sc.y, bv.y);
            mu = sm.z * inv;       sc.z = rsqrtf(fmaf(-mu, mu, sq.z * inv) + 1e-5f) * gv.z; sh.z = fmaf(-mu, sc.z, bv.z);
            mu = sm.w * inv;       sc.w = rsqrtf(fmaf(-mu, mu, sq.w * inv) + 1e-5f) * gv.w; sh.w = fmaf(-mu, sc.w, bv.w);
            sc4[tid] = sc; sh4[tid] = sh;
        }
        __syncthreads();
    }
    const float4* xa = (const float4*)(src + (t * NN + nt * 32) * FF);
    const float4* xb = (const float4*)(src + (t * NN + mt * 32) * FF);
#pragma unroll
    for (int i = 0; i < 4; ++i) {
        int idx = tid + i * 256;
        int r = idx >> 5, k = idx & 31;
        float4 a = xa[idx], b = xb[idx];
        if (BN) {
            float4 sc = sc4[k], sh = sh4[k];
            a.x = lrelu(fmaf(a.x, sc.x, sh.x)); a.y = lrelu(fmaf(a.y, sc.y, sh.y));
            a.z = lrelu(fmaf(a.z, sc.z, sh.z)); a.w = lrelu(fmaf(a.w, sc.w, sh.w));
            b.x = lrelu(fmaf(b.x, sc.x, sh.x)); b.y = lrelu(fmaf(b.y, sc.y, sh.y));
            b.z = lrelu(fmaf(b.z, sc.z, sh.z)); b.w = lrelu(fmaf(b.w, sc.w, sh.w));
        }
        As[r * 33 + k] = a;
        Bs[r * 33 + k] = b;
    }
    __syncthreads();
    // two warps compute row norms (independent-chain accumulate)
    if (tid < 64) {
        int r = tid & 31;
        const float4* s4 = (tid < 32) ? As : Bs;
        float4 s = {0.f, 0.f, 0.f, 0.f};
#pragma unroll 8
        for (int k = 0; k < 32; ++k) { float4 v = s4[r * 33 + k]; fma4(v, v, s); }
        if (tid < 32) nA[r] = sqrtf(hsum4(s)); else nB[r] = sqrtf(hsum4(s));
    }
    int ra = tid & 15, cb = tid >> 4;     // rows {ra, ra+16}, cols {cb, cb+16}
    float4 s00 = {0,0,0,0}, s01 = {0,0,0,0}, s10 = {0,0,0,0}, s11 = {0,0,0,0};
#pragma unroll 8
    for (int k = 0; k < 32; ++k) {
        float4 r0 = As[ra * 33 + k], r1 = As[(ra + 16) * 33 + k];
        float4 q0 = Bs[cb * 33 + k], q1 = Bs[(cb + 16) * 33 + k];
        fma4(r0, q0, s00); fma4(r0, q1, s01);
        fma4(r1, q0, s10); fma4(r1, q1, s11);
    }
    __syncthreads();   // norms visible
    float na[2] = { nA[ra], nA[ra + 16] };
    float nb[2] = { nB[cb], nB[cb + 16] };
    float acc[2][2] = { {hsum4(s00), hsum4(s01)}, {hsum4(s10), hsum4(s11)} };
    long ob0 = (long)(t * 2 + 0) * NN * NN;
    long ob1 = (long)(t * 2 + 1) * NN * NN;
#pragma unroll
    for (int k = 0; k < 2; ++k) {
#pragma unroll
        for (int q = 0; q < 2; ++q) {
            int n = nt * 32 + ra + k * 16;
            int m = mt * 32 + cb + q * 16;
            float sim = __fdividef(acc[k][q], na[k] * nb[q] + 1e-6f);
            float v0 = fminf(fmaxf(sim, 0.0f), 1.0f);
            float v1 = fminf(fmaxf(1.0f - sim, 0.0f), 1.0f);
            out[ob0 + n * NN + m] = v0;
            out[ob1 + n * NN + m] = v1;
        }
    }
    if (BN && nt == mt) {
        float4* xo = (float4*)(xout + (t * NN + nt * 32) * FF);
#pragma unroll
        for (int i = 0; i < 4; ++i) {
            int idx = tid + i * 256;
            int r = idx >> 5, k = idx & 31;
            xo[idx] = As[r * 33 + k];
        }
    }
}

// ---- standalone sim_cal (BN path): grid (16 tiles, T), 256 threads ----
__global__ void __launch_bounds__(256) k_simcal(
        const float* __restrict__ src, const float* __restrict__ stats,
        const float* __restrict__ gamma, const float* __restrict__ beta,
        float* __restrict__ xout, float* __restrict__ out) {
    simcal_body<true>(src, stats, gamma, beta, xout, out,
                      blockIdx.y, blockIdx.x, threadIdx.x);
}

// ---- fused: layer-0 edge pass (z<4, 8 i-rows/block) + input sim_cal (z==4) ----
// grid (16, T, 5), 256 threads
__global__ void __launch_bounds__(256) k_fused0(
        const float* __restrict__ node, const float* __restrict__ edge,
        const float* __restrict__ ew, const float* __restrict__ eb,
        float* __restrict__ stats, float* __restrict__ out) {
    int z = blockIdx.z;
    int tid = threadIdx.x;
    if (z == 4) {   // input sim_cal tile
        simcal_body<false>(node, nullptr, nullptr, nullptr, nullptr, out,
                           blockIdx.y, blockIdx.x, tid);
        return;
    }
    if (z == 0 && blockIdx.x == 0 && blockIdx.y == 0)
        stats[tid] = 0.0f;   // 256 threads cover sum0+sumsq0
    int t = blockIdx.y;
    int lane = tid & 31, w = tid >> 5;
    int i = blockIdx.x * 8 + w;
    int j0 = z * 32;
    float w0 = ew[0], w1 = ew[1], w2 = ew[2], b = eb[0];
    const float4* x4 = (const float4*)(node + t * NN * FF);
    float4 xi = x4[i * 32 + lane];
    float cx = fmaf(w0 + w1, xi.x, b), cy = fmaf(w0 + w1, xi.y, b);
    float cz = fmaf(w0 + w1, xi.z, b), cw_ = fmaf(w0 + w1, xi.w, b);
    const float4* e4 = (const float4*)(edge + ((size_t)(t * NN + i) * NN) * FF);
    float ax = 0.f, ay = 0.f, az = 0.f, aw = 0.f;
#pragma unroll 8
    for (int jj = 0; jj < 32; ++jj) {
        int j = j0 + jj;
        float4 e = __ldcs(&e4[j * 32 + lane]);
        float4 xj = x4[j * 32 + lane];
        ax += tanh_fast(fmaf(w2, e.x, fmaf(-w1, xj.x, cx)));
        ay += tanh_fast(fmaf(w2, e.y, fmaf(-w1, xj.y, cy)));
        az += tanh_fast(fmaf(w2, e.z, fmaf(-w1, xj.z, cz)));
        aw += tanh_fast(fmaf(w2, e.w, fmaf(-w1, xj.w, cw_)));
    }
    if ((i >> 5) == z) {   // subtract diagonal if i falls in this quarter
        float4 eii = e4[i * 32 + lane];
        ax -= tanh_fast(fmaf(w2, eii.x, fmaf(-w1, xi.x, cx)));
        ay -= tanh_fast(fmaf(w2, eii.y, fmaf(-w1, xi.y, cy)));
        az -= tanh_fast(fmaf(w2, eii.z, fmaf(-w1, xi.z, cz)));
        aw -= tanh_fast(fmaf(w2, eii.w, fmaf(-w1, xi.w, cw_)));
    }
    float4 acc; acc.x = ax; acc.y = ay; acc.z = az; acc.w = aw;
    ((float4*)(g_aggr + z * SEG + (t * NN + i) * FF))[lane] = acc;
}

// ---- layer-1: recompute e0 on the fly, chain layer-1 tanh, partial-aggregate ----
// grid (32, T, 4), block 128
__global__ void __launch_bounds__(128) k_edge1(
        const float* __restrict__ node0, const float* __restrict__ node1,
        const float* __restrict__ edge,
        const float* __restrict__ ew, const float* __restrict__ eb,
        float* __restrict__ stats) {
    int z = blockIdx.z;
    if (z == 0 && blockIdx.x == 0 && blockIdx.y == 0) {
        stats[threadIdx.x] = 0.0f; stats[threadIdx.x + 128] = 0.0f;
    }
    int t = blockIdx.y;
    int lane = threadIdx.x & 31, w = threadIdx.x >> 5;
    int i = blockIdx.x * 4 + w;
    int j0 = z * 32;
    float w00 = ew[0], w01 = ew[1], w02 = ew[2], b0 = eb[0];
    float w10 = ew[3], w11 = ew[4], w12 = ew[5], b1 = eb[1];
    const float4* x04 = (const float4*)(node0 + t * NN * FF);
    const float4* x14 = (const float4*)(node1 + t * NN * FF);
    float4 xi0 = x04[i * 32 + lane];
    float4 xi1 = x14[i * 32 + lane];
    float c0x = fmaf(w00 + w01, xi0.x, b0), c0y = fmaf(w00 + w01, xi0.y, b0);
    float c0z = fmaf(w00 + w01, xi0.z, b0), c0w = fmaf(w00 + w01, xi0.w, b0);
    float c1x = fmaf(w10 + w11, xi1.x, b1), c1y = fmaf(w10 + w11, xi1.y, b1);
    float c1z = fmaf(w10 + w11, xi1.z, b1), c1w = fmaf(w10 + w11, xi1.w, b1);
    const float4* e4 = (const float4*)(edge + ((size_t)(t * NN + i) * NN) * FF);
    float ax = 0.f, ay = 0.f, az = 0.f, aw = 0.f;
#pragma unroll 4
    for (int jj = 0; jj < 32; ++jj) {
        int j = j0 + jj;
        float4 e  = __ldcs(&e4[j * 32 + lane]);
        float4 x0 = x04[j * 32 + lane];
        float4 x1 = x14[j * 32 + lane];
        float e0x = tanh_fast(fmaf(w02, e.x, fmaf(-w01, x0.x, c0x)));
        float e0y = tanh_fast(fmaf(w02, e.y, fmaf(-w01, x0.y, c0y)));
        float e0z = tanh_fast(fmaf(w02, e.z, fmaf(-w01, x0.z, c0z)));
        float e0w = tanh_fast(fmaf(w02, e.w, fmaf(-w01, x0.w, c0w)));
        ax += tanh_fast(fmaf(w12, e0x, fmaf(-w11, x1.x, c1x)));
        ay += tanh_fast(fmaf(w12, e0y, fmaf(-w11, x1.y, c1y)));
        az += tanh_fast(fmaf(w12, e0z, fmaf(-w11, x1.z, c1z)));
        aw += tanh_fast(fmaf(w12, e0w, fmaf(-w11, x1.w, c1w)));
    }
    if ((i >> 5) == z) {
        float4 e = e4[i * 32 + lane];
        float e0x = tanh_fast(fmaf(w02, e.x, fmaf(-w01, xi0.x, c0x)));
        float e0y = tanh_fast(fmaf(w02, e.y, fmaf(-w01, xi0.y, c0y)));
        float e0z = tanh_fast(fmaf(w02, e.z, fmaf(-w01, xi0.z, c0z)));
        float e0w = tanh_fast(fmaf(w02, e.w, fmaf(-w01, xi0.w, c0w)));
        ax -= tanh_fast(fmaf(w12, e0x, fmaf(-w11, xi1.x, c1x)));
        ay -= tanh_fast(fmaf(w12, e0y, fmaf(-w11, xi1.y, c1y)));
        az -= tanh_fast(fmaf(w12, e0z, fmaf(-w11, xi1.z, c1z)));
        aw -= tanh_fast(fmaf(w12, e0w, fmaf(-w11, xi1.w, c1w)));
    }
    float4 acc; acc.x = ax; acc.y = ay; acc.z = az; acc.w = aw;
    ((float4*)(g_aggr + z * SEG + (t * NN + i) * FF))[lane] = acc;
}

// ---- node GEMM (all-float4 mainloop) + fused BN-stat accumulation ----
// grid T*8 (16-row tiles), 256 threads; dyn smem: Ws4[128][33] + hs4[16][33]
__global__ void __launch_bounds__(256) k_gemm(
        const float* __restrict__ x, const float* __restrict__ cw,
        const float* __restrict__ W, float* __restrict__ y, float* __restrict__ stats) {
    extern __shared__ float4 sm4[];
    float4* Ws = sm4;               // [g][k], pitch 33 float4
    float4* hs = sm4 + 128 * 33;    // [r][k], pitch 33 float4
    float c0 = cw[0], c1 = cw[1];
    int t = blockIdx.x >> 3;
    int r0 = (blockIdx.x & 7) * 16;
    int tid = threadIdx.x;
    const float4* W4 = (const float4*)W;
#pragma unroll
    for (int i = 0; i < 16; ++i) {
        int idx = tid + i * 256;
        int g = idx >> 5, k = idx & 31;
        Ws[g * 33 + k] = W4[idx];
    }
    const float4* x4 = (const float4*)(x + (t * NN + r0) * FF);
    const float4* a4 = (const float4*)(g_aggr + 0 * SEG + (t * NN + r0) * FF);
    const float4* b4 = (const float4*)(g_aggr + 1 * SEG + (t * NN + r0) * FF);
    const float4* c4 = (const float4*)(g_aggr + 2 * SEG + (t * NN + r0) * FF);
    const float4* d4 = (const float4*)(g_aggr + 3 * SEG + (t * NN + r0) * FF);
#pragma unroll
    for (int i = 0; i < 2; ++i) {
        int idx = tid + i * 256;
        int r = idx >> 5, k = idx & 31;
        float4 xv = x4[idx], av = a4[idx], bv = b4[idx], cv = c4[idx], dv = d4[idx], h;
        h.x = lrelu(fmaf(c1, (av.x + bv.x) + (cv.x + dv.x), c0 * xv.x));
        h.y = lrelu(fmaf(c1, (av.y + bv.y) + (cv.y + dv.y), c0 * xv.y));
        h.z = lrelu(fmaf(c1, (av.z + bv.z) + (cv.z + dv.z), c0 * xv.z));
        h.w = lrelu(fmaf(c1, (av.w + bv.w) + (cv.w + dv.w), c0 * xv.w));
        hs[r * 33 + k] = h;
    }
    __syncthreads();
    int rt = tid & 7, gt = tid >> 3;   // rows {rt, rt+8}, g's gt*4..+3
    float acc[2][4] = { {0.f,0.f,0.f,0.f}, {0.f,0.f,0.f,0.f} };
#pragma unroll 4
    for (int k = 0; k < 32; ++k) {
        float4 a0 = hs[rt * 33 + k];
        float4 a1 = hs[(rt + 8) * 33 + k];
#pragma unroll
        for (int q = 0; q < 4; ++q) {
            float4 wv = Ws[(gt * 4 + q) * 33 + k];
            acc[0][q] = fmaf(a0.x, wv.x, fmaf(a0.y, wv.y, fmaf(a0.z, wv.z, fmaf(a0.w, wv.w, acc[0][q]))));
            acc[1][q] = fmaf(a1.x, wv.x, fmaf(a1.y, wv.y, fmaf(a1.z, wv.z, fmaf(a1.w, wv.w, acc[1][q]))));
        }
    }
    float4 v0; v0.x = acc[0][0]; v0.y = acc[0][1]; v0.z = acc[0][2]; v0.w = acc[0][3];
    float4 v1; v1.x = acc[1][0]; v1.y = acc[1][1]; v1.z = acc[1][2]; v1.w = acc[1][3];
    *(float4*)(y + (t * NN + r0 + rt) * FF + gt * 4) = v0;
    *(float4*)(y + (t * NN + r0 + rt + 8) * FF + gt * 4) = v1;
#pragma unroll
    for (int q = 0; q < 4; ++q) {
        float s  = acc[0][q] + acc[1][q];
        float ss = fmaf(acc[0][q], acc[0][q], acc[1][q] * acc[1][q]);
#pragma unroll
        for (int o = 4; o; o >>= 1) {
            s  += __shfl_down_sync(0xffffffffu, s,  o, 8);
            ss += __shfl_down_sync(0xffffffffu, ss, o, 8);
        }
        if (rt == 0) {
            int g = gt * 4 + q;
            atomicAdd(&stats[g], s);
            atomicAdd(&stats[FF + g], ss);
        }
    }
}

extern "C" void kernel_launch(void* const* d_in, const int* in_sizes, int n_in,
                              void* d_out, int out_size) {
    const float* node  = (const float*)d_in[0];
    const float* edge  = (const float*)d_in[1];
    const float* ew    = (const float*)d_in[2];   // [L,3]
    const float* ebv   = (const float*)d_in[3];   // [L]
    const float* cw    = (const float*)d_in[4];   // [L,2]
    const float* nw    = (const float*)d_in[5];   // [L,F,F]
    const float* gamma = (const float*)d_in[6];   // [L,F]
    const float* beta  = (const float*)d_in[7];   // [L,F]
    float* out = (float*)d_out;

    void *p1, *p2, *py, *ps;
    cudaGetSymbolAddress(&p1, g_node1);
    cudaGetSymbolAddress(&p2, g_node2);
    cudaGetSymbolAddress(&py, g_y);
    cudaGetSymbolAddress(&ps, g_stats);
    float* node1 = (float*)p1;
    float* node2 = (float*)p2;
    float* y     = (float*)py;
    float* st    = (float*)ps;

    size_t gemm_smem = (size_t)(128 * 33 + 16 * 33) * sizeof(float4);
    cudaFuncSetAttribute(k_gemm, cudaFuncAttributeMaxDynamicSharedMemorySize, (int)gemm_smem);

    const int OUTBLK = TT * 2 * NN * NN;

    // ---- layer 0 (input sim_cal fused into the edge pass as z==4) ----
    k_fused0<<<dim3(16, TT, 5), 256>>>(node, edge, ew, ebv, st, out);
    k_gemm<<<TT * 8, 256, gemm_smem>>>(node, cw, nw, y, st);
    // BN-apply fused into simcal; diagonal tiles write node1
    k_simcal<<<dim3(16, TT), 256>>>(y, st, gamma, beta, node1, out + OUTBLK);

    // ---- layer 1 (recompute layer-0 edges on the fly) ----
    k_edge1<<<dim3(32, TT, 4), 128>>>(node, node1, edge, ew, ebv, st + 2 * FF);
    k_gemm<<<TT * 8, 256, gemm_smem>>>(node1, cw + 2, nw + FF * FF, y, st + 2 * FF);
    k_simcal<<<dim3(16, TT), 256>>>(y, st + 2 * FF, gamma + FF, beta + FF, node2,
                                    out + 2 * OUTBLK);
}

// round 16
// speedup vs baseline: 1.5379x; 1.0264x over previous
#include <cuda_runtime.h>
#include <cuda_fp16.h>
#include <math.h>

#define TT 16
#define NN 128
#define FF 128
#define TN (TT*NN)
#define SEG (TT*NN*FF)

// ---- scratch (__device__ globals; no allocation allowed) ----
__device__ float g_aggr[4*SEG];       // 4 j-quarter partial aggregates
__device__ float g_y[SEG];
__device__ float g_node1[SEG];
__device__ float g_node2[SEG];
__device__ float g_stats[4*FF];       // [sum0(128), sumsq0(128), sum1, sumsq1]
__device__ __half g_e0[(size_t)TT*NN*NN*FF];   // layer-0 tanh output, fp16 (67MB)

__device__ __forceinline__ float tanh_fast(float x) {
    float y; asm("tanh.approx.f32 %0, %1;" : "=f"(y) : "f"(x)); return y;
}
__device__ __forceinline__ float lrelu(float v) { return v >= 0.0f ? v : 0.01f * v; }
__device__ __forceinline__ void fma4(float4 a, float4 b, float4& s) {
    s.x = fmaf(a.x, b.x, s.x); s.y = fmaf(a.y, b.y, s.y);
    s.z = fmaf(a.z, b.z, s.z); s.w = fmaf(a.w, b.w, s.w);
}
__device__ __forceinline__ float hsum4(float4 s) { return (s.x + s.y) + (s.z + s.w); }

// ---- sim_cal body: 32x32 tile, 2x2/thread, 16 independent FMA chains ----
template<bool BN>
__device__ __forceinline__ void simcal_body(
        const float* __restrict__ src, const float* __restrict__ stats,
        const float* __restrict__ gamma, const float* __restrict__ beta,
        float* __restrict__ xout, float* __restrict__ out,
        int t, int tilex, int tid) {
    __shared__ float4 As[32*33], Bs[32*33];
    __shared__ float nA[32], nB[32];
    __shared__ float4 sc4[32], sh4[32];
    int nt = tilex >> 2, mt = tilex & 3;
    if (BN) {
        if (tid < 32) {
            const float inv = 1.0f / (float)TN;
            float4 sm = ((const float4*)stats)[tid];
            float4 sq = ((const float4*)(stats + FF))[tid];
            float4 gv = ((const float4*)gamma)[tid];
            float4 bv = ((const float4*)beta)[tid];
            float4 sc, sh;
            float mu = sm.x * inv; sc.x = rsqrtf(fmaf(-mu, mu, sq.x * inv) + 1e-5f) * gv.x; sh.x = fmaf(-mu, sc.x, bv.x);
            mu = sm.y * inv;       sc.y = rsqrtf(fmaf(-mu, mu, sq.y * inv) + 1e-5f) * gv.y; sh.y = fmaf(-mu, sc.y, bv.y);
            mu = sm.z * inv;       sc.z = rsqrtf(fmaf(-mu, mu, sq.z * inv) + 1e-5f) * gv.z; sh.z = fmaf(-mu, sc.z, bv.z);
            mu = sm.w * inv;       sc.w = rsqrtf(fmaf(-mu, mu, sq.w * inv) + 1e-5f) * gv.w; sh.w = fmaf(-mu, sc.w, bv.w);
            sc4[tid] = sc; sh4[tid] = sh;
        }
        __syncthreads();
    }
    const float4* xa = (const float4*)(src + (t * NN + nt * 32) * FF);
    const float4* xb = (const float4*)(src + (t * NN + mt * 32) * FF);
#pragma unroll
    for (int i = 0; i < 4; ++i) {
        int idx = tid + i * 256;
        int r = idx >> 5, k = idx & 31;
        float4 a = xa[idx], b = xb[idx];
        if (BN) {
            float4 sc = sc4[k], sh = sh4[k];
            a.x = lrelu(fmaf(a.x, sc.x, sh.x)); a.y = lrelu(fmaf(a.y, sc.y, sh.y));
            a.z = lrelu(fmaf(a.z, sc.z, sh.z)); a.w = lrelu(fmaf(a.w, sc.w, sh.w));
            b.x = lrelu(fmaf(b.x, sc.x, sh.x)); b.y = lrelu(fmaf(b.y, sc.y, sh.y));
            b.z = lrelu(fmaf(b.z, sc.z, sh.z)); b.w = lrelu(fmaf(b.w, sc.w, sh.w));
        }
        As[r * 33 + k] = a;
        Bs[r * 33 + k] = b;
    }
    __syncthreads();
    if (tid < 64) {
        int r = tid & 31;
        const float4* s4 = (tid < 32) ? As : Bs;
        float4 s = {0.f, 0.f, 0.f, 0.f};
#pragma unroll 8
        for (int k = 0; k < 32; ++k) { float4 v = s4[r * 33 + k]; fma4(v, v, s); }
        if (tid < 32) nA[r] = sqrtf(hsum4(s)); else nB[r] = sqrtf(hsum4(s));
    }
    int ra = tid & 15, cb = tid >> 4;
    float4 s00 = {0,0,0,0}, s01 = {0,0,0,0}, s10 = {0,0,0,0}, s11 = {0,0,0,0};
#pragma unroll 8
    for (int k = 0; k < 32; ++k) {
        float4 r0 = As[ra * 33 + k], r1 = As[(ra + 16) * 33 + k];
        float4 q0 = Bs[cb * 33 + k], q1 = Bs[(cb + 16) * 33 + k];
        fma4(r0, q0, s00); fma4(r0, q1, s01);
        fma4(r1, q0, s10); fma4(r1, q1, s11);
    }
    __syncthreads();
    float na[2] = { nA[ra], nA[ra + 16] };
    float nb[2] = { nB[cb], nB[cb + 16] };
    float acc[2][2] = { {hsum4(s00), hsum4(s01)}, {hsum4(s10), hsum4(s11)} };
    long ob0 = (long)(t * 2 + 0) * NN * NN;
    long ob1 = (long)(t * 2 + 1) * NN * NN;
#pragma unroll
    for (int k = 0; k < 2; ++k) {
#pragma unroll
        for (int q = 0; q < 2; ++q) {
            int n = nt * 32 + ra + k * 16;
            int m = mt * 32 + cb + q * 16;
            float sim = __fdividef(acc[k][q], na[k] * nb[q] + 1e-6f);
            float v0 = fminf(fmaxf(sim, 0.0f), 1.0f);
            float v1 = fminf(fmaxf(1.0f - sim, 0.0f), 1.0f);
            out[ob0 + n * NN + m] = v0;
            out[ob1 + n * NN + m] = v1;
        }
    }
    if (BN && nt == mt) {
        float4* xo = (float4*)(xout + (t * NN + nt * 32) * FF);
#pragma unroll
        for (int i = 0; i < 4; ++i) {
            int idx = tid + i * 256;
            int r = idx >> 5, k = idx & 31;
            xo[idx] = As[r * 33 + k];
        }
    }
}

// ---- standalone sim_cal (BN path): grid (16 tiles, T), 256 threads ----
__global__ void __launch_bounds__(256) k_simcal(
        const float* __restrict__ src, const float* __restrict__ stats,
        const float* __restrict__ gamma, const float* __restrict__ beta,
        float* __restrict__ xout, float* __restrict__ out) {
    simcal_body<true>(src, stats, gamma, beta, xout, out,
                      blockIdx.y, blockIdx.x, threadIdx.x);
}

// ---- fused: layer-0 edge pass (z<4) + e0 fp16 store + input sim_cal (z==4) ----
// grid (16, T, 5), 256 threads
__global__ void __launch_bounds__(256) k_fused0(
        const float* __restrict__ node, const float* __restrict__ edge,
        const float* __restrict__ ew, const float* __restrict__ eb,
        float* __restrict__ stats, float* __restrict__ out) {
    int z = blockIdx.z;
    int tid = threadIdx.x;
    if (z == 4) {
        simcal_body<false>(node, nullptr, nullptr, nullptr, nullptr, out,
                           blockIdx.y, blockIdx.x, tid);
        return;
    }
    if (z == 0 && blockIdx.x == 0 && blockIdx.y == 0)
        stats[tid] = 0.0f;
    int t = blockIdx.y;
    int lane = tid & 31, w = tid >> 5;
    int i = blockIdx.x * 8 + w;
    int j0 = z * 32;
    float w0 = ew[0], w1 = ew[1], w2 = ew[2], b = eb[0];
    const float4* x4 = (const float4*)(node + t * NN * FF);
    float4 xi = x4[i * 32 + lane];
    float cx = fmaf(w0 + w1, xi.x, b), cy = fmaf(w0 + w1, xi.y, b);
    float cz = fmaf(w0 + w1, xi.z, b), cw_ = fmaf(w0 + w1, xi.w, b);
    const float4* e4 = (const float4*)(edge + ((size_t)(t * NN + i) * NN) * FF);
    __half* e0row = g_e0 + ((size_t)(t * NN + i) * NN) * FF;
    float ax = 0.f, ay = 0.f, az = 0.f, aw = 0.f;
#pragma unroll 8
    for (int jj = 0; jj < 32; ++jj) {
        int j = j0 + jj;
        float4 e = __ldcs(&e4[j * 32 + lane]);
        float4 xj = x4[j * 32 + lane];
        float rx = tanh_fast(fmaf(w2, e.x, fmaf(-w1, xj.x, cx)));
        float ry = tanh_fast(fmaf(w2, e.y, fmaf(-w1, xj.y, cy)));
        float rz = tanh_fast(fmaf(w2, e.z, fmaf(-w1, xj.z, cz)));
        float rw = tanh_fast(fmaf(w2, e.w, fmaf(-w1, xj.w, cw_)));
        ax += rx; ay += ry; az += rz; aw += rw;
        __half2 h01 = __floats2half2_rn(rx, ry);
        __half2 h23 = __floats2half2_rn(rz, rw);
        uint2 u;
        u.x = *reinterpret_cast<unsigned*>(&h01);
        u.y = *reinterpret_cast<unsigned*>(&h23);
        *reinterpret_cast<uint2*>(e0row + (size_t)j * FF + lane * 4) = u;
    }
    if ((i >> 5) == z) {   // subtract diagonal if i falls in this quarter
        float4 eii = e4[i * 32 + lane];
        ax -= tanh_fast(fmaf(w2, eii.x, fmaf(-w1, xi.x, cx)));
        ay -= tanh_fast(fmaf(w2, eii.y, fmaf(-w1, xi.y, cy)));
        az -= tanh_fast(fmaf(w2, eii.z, fmaf(-w1, xi.z, cz)));
        aw -= tanh_fast(fmaf(w2, eii.w, fmaf(-w1, xi.w, cw_)));
    }
    float4 acc; acc.x = ax; acc.y = ay; acc.z = az; acc.w = aw;
    ((float4*)(g_aggr + z * SEG + (t * NN + i) * FF))[lane] = acc;
}

// ---- layer-1: read fp16 e0, single tanh chain, partial-aggregate ----
// grid (32, T, 4), block 128
__global__ void __launch_bounds__(128) k_edge1(
        const float* __restrict__ node1,
        const float* __restrict__ ew, const float* __restrict__ eb,
        float* __restrict__ stats) {
    int z = blockIdx.z;
    if (z == 0 && blockIdx.x == 0 && blockIdx.y == 0) {
        stats[threadIdx.x] = 0.0f; stats[threadIdx.x + 128] = 0.0f;
    }
    int t = blockIdx.y;
    int lane = threadIdx.x & 31, w = threadIdx.x >> 5;
    int i = blockIdx.x * 4 + w;
    int j0 = z * 32;
    float w10 = ew[3], w11 = ew[4], w12 = ew[5], b1 = eb[1];
    const float4* x14 = (const float4*)(node1 + t * NN * FF);
    float4 xi1 = x14[i * 32 + lane];
    float c1x = fmaf(w10 + w11, xi1.x, b1), c1y = fmaf(w10 + w11, xi1.y, b1);
    float c1z = fmaf(w10 + w11, xi1.z, b1), c1w = fmaf(w10 + w11, xi1.w, b1);
    const __half* e0row = g_e0 + ((size_t)(t * NN + i) * NN) * FF;
    float ax = 0.f, ay = 0.f, az = 0.f, aw = 0.f;
#pragma unroll 8
    for (int jj = 0; jj < 32; ++jj) {
        int j = j0 + jj;
        uint2 u = *reinterpret_cast<const uint2*>(e0row + (size_t)j * FF + lane * 4);
        __half2 h01 = *reinterpret_cast<__half2*>(&u.x);
        __half2 h23 = *reinterpret_cast<__half2*>(&u.y);
        float2 f01 = __half22float2(h01);
        float2 f23 = __half22float2(h23);
        float4 x1 = x14[j * 32 + lane];
        ax += tanh_fast(fmaf(w12, f01.x, fmaf(-w11, x1.x, c1x)));
        ay += tanh_fast(fmaf(w12, f01.y, fmaf(-w11, x1.y, c1y)));
        az += tanh_fast(fmaf(w12, f23.x, fmaf(-w11, x1.z, c1z)));
        aw += tanh_fast(fmaf(w12, f23.y, fmaf(-w11, x1.w, c1w)));
    }
    if ((i >> 5) == z) {   // subtract diagonal (same stored value as added)
        uint2 u = *reinterpret_cast<const uint2*>(e0row + (size_t)i * FF + lane * 4);
        __half2 h01 = *reinterpret_cast<__half2*>(&u.x);
        __half2 h23 = *reinterpret_cast<__half2*>(&u.y);
        float2 f01 = __half22float2(h01);
        float2 f23 = __half22float2(h23);
        ax -= tanh_fast(fmaf(w12, f01.x, fmaf(-w11, xi1.x, c1x)));
        ay -= tanh_fast(fmaf(w12, f01.y, fmaf(-w11, xi1.y, c1y)));
        az -= tanh_fast(fmaf(w12, f23.x, fmaf(-w11, xi1.z, c1z)));
        aw -= tanh_fast(fmaf(w12, f23.y, fmaf(-w11, xi1.w, c1w)));
    }
    float4 acc; acc.x = ax; acc.y = ay; acc.z = az; acc.w = aw;
    ((float4*)(g_aggr + z * SEG + (t * NN + i) * FF))[lane] = acc;
}

// ---- node GEMM (all-float4 mainloop) + fused BN-stat accumulation ----
__global__ void __launch_bounds__(256) k_gemm(
        const float* __restrict__ x, const float* __restrict__ cw,
        const float* __restrict__ W, float* __restrict__ y, float* __restrict__ stats) {
    extern __shared__ float4 sm4[];
    float4* Ws = sm4;               // [g][k], pitch 33 float4
    float4* hs = sm4 + 128 * 33;    // [r][k], pitch 33 float4
    float c0 = cw[0], c1 = cw[1];
    int t = blockIdx.x >> 3;
    int r0 = (blockIdx.x & 7) * 16;
    int tid = threadIdx.x;
    const float4* W4 = (const float4*)W;
#pragma unroll
    for (int i = 0; i < 16; ++i) {
        int idx = tid + i * 256;
        int g = idx >> 5, k = idx & 31;
        Ws[g * 33 + k] = W4[idx];
    }
    const float4* x4 = (const float4*)(x + (t * NN + r0) * FF);
    const float4* a4 = (const float4*)(g_aggr + 0 * SEG + (t * NN + r0) * FF);
    const float4* b4 = (const float4*)(g_aggr + 1 * SEG + (t * NN + r0) * FF);
    const float4* c4 = (const float4*)(g_aggr + 2 * SEG + (t * NN + r0) * FF);
    const float4* d4 = (const float4*)(g_aggr + 3 * SEG + (t * NN + r0) * FF);
#pragma unroll
    for (int i = 0; i < 2; ++i) {
        int idx = tid + i * 256;
        int r = idx >> 5, k = idx & 31;
        float4 xv = x4[idx], av = a4[idx], bv = b4[idx], cv = c4[idx], dv = d4[idx], h;
        h.x = lrelu(fmaf(c1, (av.x + bv.x) + (cv.x + dv.x), c0 * xv.x));
        h.y = lrelu(fmaf(c1, (av.y + bv.y) + (cv.y + dv.y), c0 * xv.y));
        h.z = lrelu(fmaf(c1, (av.z + bv.z) + (cv.z + dv.z), c0 * xv.z));
        h.w = lrelu(fmaf(c1, (av.w + bv.w) + (cv.w + dv.w), c0 * xv.w));
        hs[r * 33 + k] = h;
    }
    __syncthreads();
    int rt = tid & 7, gt = tid >> 3;
    float acc[2][4] = { {0.f,0.f,0.f,0.f}, {0.f,0.f,0.f,0.f} };
#pragma unroll 4
    for (int k = 0; k < 32; ++k) {
        float4 a0 = hs[rt * 33 + k];
        float4 a1 = hs[(rt + 8) * 33 + k];
#pragma unroll
        for (int q = 0; q < 4; ++q) {
            float4 wv = Ws[(gt * 4 + q) * 33 + k];
            acc[0][q] = fmaf(a0.x, wv.x, fmaf(a0.y, wv.y, fmaf(a0.z, wv.z, fmaf(a0.w, wv.w, acc[0][q]))));
            acc[1][q] = fmaf(a1.x, wv.x, fmaf(a1.y, wv.y, fmaf(a1.z, wv.z, fmaf(a1.w, wv.w, acc[1][q]))));
        }
    }
    float4 v0; v0.x = acc[0][0]; v0.y = acc[0][1]; v0.z = acc[0][2]; v0.w = acc[0][3];
    float4 v1; v1.x = acc[1][0]; v1.y = acc[1][1]; v1.z = acc[1][2]; v1.w = acc[1][3];
    *(float4*)(y + (t * NN + r0 + rt) * FF + gt * 4) = v0;
    *(float4*)(y + (t * NN + r0 + rt + 8) * FF + gt * 4) = v1;
#pragma unroll
    for (int q = 0; q < 4; ++q) {
        float s  = acc[0][q] + acc[1][q];
        float ss = fmaf(acc[0][q], acc[0][q], acc[1][q] * acc[1][q]);
#pragma unroll
        for (int o = 4; o; o >>= 1) {
            s  += __shfl_down_sync(0xffffffffu, s,  o, 8);
            ss += __shfl_down_sync(0xffffffffu, ss, o, 8);
        }
        if (rt == 0) {
            int g = gt * 4 + q;
            atomicAdd(&stats[g], s);
            atomicAdd(&stats[FF + g], ss);
        }
    }
}

extern "C" void kernel_launch(void* const* d_in, const int* in_sizes, int n_in,
                              void* d_out, int out_size) {
    const float* node  = (const float*)d_in[0];
    const float* edge  = (const float*)d_in[1];
    const float* ew    = (const float*)d_in[2];   // [L,3]
    const float* ebv   = (const float*)d_in[3];   // [L]
    const float* cw    = (const float*)d_in[4];   // [L,2]
    const float* nw    = (const float*)d_in[5];   // [L,F,F]
    const float* gamma = (const float*)d_in[6];   // [L,F]
    const float* beta  = (const float*)d_in[7];   // [L,F]
    float* out = (float*)d_out;

    void *p1, *p2, *py, *ps;
    cudaGetSymbolAddress(&p1, g_node1);
    cudaGetSymbolAddress(&p2, g_node2);
    cudaGetSymbolAddress(&py, g_y);
    cudaGetSymbolAddress(&ps, g_stats);
    float* node1 = (float*)p1;
    float* node2 = (float*)p2;
    float* y     = (float*)py;
    float* st    = (float*)ps;

    size_t gemm_smem = (size_t)(128 * 33 + 16 * 33) * sizeof(float4);
    cudaFuncSetAttribute(k_gemm, cudaFuncAttributeMaxDynamicSharedMemorySize, (int)gemm_smem);

    const int OUTBLK = TT * 2 * NN * NN;

    // ---- layer 0 (input sim_cal fused as z==4; e0 stored fp16) ----
    k_fused0<<<dim3(16, TT, 5), 256>>>(node, edge, ew, ebv, st, out);
    k_gemm<<<TT * 8, 256, gemm_smem>>>(node, cw, nw, y, st);
    k_simcal<<<dim3(16, TT), 256>>>(y, st, gamma, beta, node1, out + OUTBLK);

    // ---- layer 1 (reads stored fp16 e0; half the tanh work) ----
    k_edge1<<<dim3(32, TT, 4), 128>>>(node1, ew, ebv, st + 2 * FF);
    k_gemm<<<TT * 8, 256, gemm_smem>>>(node1, cw + 2, nw + FF * FF, y, st + 2 * FF);
    k_simcal<<<dim3(16, TT), 256>>>(y, st + 2 * FF, gamma + FF, beta + FF, node2,
                                    out + 2 * OUTBLK);
}

// round 17
// speedup vs baseline: 1.5607x; 1.0148x over previous
#include <cuda_runtime.h>
#include <cuda_fp16.h>
#include <math.h>

#define TT 16
#define NN 128
#define FF 128
#define TN (TT*NN)
#define SEG (TT*NN*FF)

// ---- scratch (__device__ globals; no allocation allowed) ----
__device__ float g_aggr[2*SEG];       // 2 j-half partial aggregates
__device__ float g_y[SEG];
__device__ float g_node1[SEG];
__device__ float g_node2[SEG];
__device__ float g_stats[4*FF];       // [sum0(128), sumsq0(128), sum1, sumsq1]
__device__ __half g_e0[(size_t)TT*NN*NN*FF];   // layer-0 tanh output, fp16 (67MB)

__device__ __forceinline__ float tanh_fast(float x) {
    float y; asm("tanh.approx.f32 %0, %1;" : "=f"(y) : "f"(x)); return y;
}
__device__ __forceinline__ __half2 tanh_fast_h2(__half2 x) {
    __half2 y;
    asm("tanh.approx.f16x2 %0, %1;"
        : "=r"(*reinterpret_cast<unsigned*>(&y))
        : "r"(*reinterpret_cast<unsigned*>(&x)));
    return y;
}
__device__ __forceinline__ float lrelu(float v) { return v >= 0.0f ? v : 0.01f * v; }
__device__ __forceinline__ void fma4(float4 a, float4 b, float4& s) {
    s.x = fmaf(a.x, b.x, s.x); s.y = fmaf(a.y, b.y, s.y);
    s.z = fmaf(a.z, b.z, s.z); s.w = fmaf(a.w, b.w, s.w);
}
__device__ __forceinline__ float hsum4(float4 s) { return (s.x + s.y) + (s.z + s.w); }

// ---- sim_cal body: 32x32 tile, 2x2/thread, 16 independent FMA chains ----
template<bool BN>
__device__ __forceinline__ void simcal_body(
        const float* __restrict__ src, const float* __restrict__ stats,
        const float* __restrict__ gamma, const float* __restrict__ beta,
        float* __restrict__ xout, float* __restrict__ out,
        int t, int tilex, int tid) {
    __shared__ float4 As[32*33], Bs[32*33];
    __shared__ float nA[32], nB[32];
    __shared__ float4 sc4[32], sh4[32];
    int nt = tilex >> 2, mt = tilex & 3;
    if (BN) {
        if (tid < 32) {
            const float inv = 1.0f / (float)TN;
            float4 sm = ((const float4*)stats)[tid];
            float4 sq = ((const float4*)(stats + FF))[tid];
            float4 gv = ((const float4*)gamma)[tid];
            float4 bv = ((const float4*)beta)[tid];
            float4 sc, sh;
            float mu = sm.x * inv; sc.x = rsqrtf(fmaf(-mu, mu, sq.x * inv) + 1e-5f) * gv.x; sh.x = fmaf(-mu, sc.x, bv.x);
            mu = sm.y * inv;       sc.y = rsqrtf(fmaf(-mu, mu, sq.y * inv) + 1e-5f) * gv.y; sh.y = fmaf(-mu, sc.y, bv.y);
            mu = sm.z * inv;       sc.z = rsqrtf(fmaf(-mu, mu, sq.z * inv) + 1e-5f) * gv.z; sh.z = fmaf(-mu, sc.z, bv.z);
            mu = sm.w * inv;       sc.w = rsqrtf(fmaf(-mu, mu, sq.w * inv) + 1e-5f) * gv.w; sh.w = fmaf(-mu, sc.w, bv.w);
            sc4[tid] = sc; sh4[tid] = sh;
        }
        __syncthreads();
    }
    const float4* xa = (const float4*)(src + (t * NN + nt * 32) * FF);
    const float4* xb = (const float4*)(src + (t * NN + mt * 32) * FF);
#pragma unroll
    for (int i = 0; i < 4; ++i) {
        int idx = tid + i * 256;
        int r = idx >> 5, k = idx & 31;
        float4 a = xa[idx], b = xb[idx];
        if (BN) {
            float4 sc = sc4[k], sh = sh4[k];
            a.x = lrelu(fmaf(a.x, sc.x, sh.x)); a.y = lrelu(fmaf(a.y, sc.y, sh.y));
            a.z = lrelu(fmaf(a.z, sc.z, sh.z)); a.w = lrelu(fmaf(a.w, sc.w, sh.w));
            b.x = lrelu(fmaf(b.x, sc.x, sh.x)); b.y = lrelu(fmaf(b.y, sc.y, sh.y));
            b.z = lrelu(fmaf(b.z, sc.z, sh.z)); b.w = lrelu(fmaf(b.w, sc.w, sh.w));
        }
        As[r * 33 + k] = a;
        Bs[r * 33 + k] = b;
    }
    __syncthreads();
    if (tid < 64) {
        int r = tid & 31;
        const float4* s4 = (tid < 32) ? As : Bs;
        float4 s = {0.f, 0.f, 0.f, 0.f};
#pragma unroll 8
        for (int k = 0; k < 32; ++k) { float4 v = s4[r * 33 + k]; fma4(v, v, s); }
        if (tid < 32) nA[r] = sqrtf(hsum4(s)); else nB[r] = sqrtf(hsum4(s));
    }
    int ra = tid & 15, cb = tid >> 4;
    float4 s00 = {0,0,0,0}, s01 = {0,0,0,0}, s10 = {0,0,0,0}, s11 = {0,0,0,0};
#pragma unroll 8
    for (int k = 0; k < 32; ++k) {
        float4 r0 = As[ra * 33 + k], r1 = As[(ra + 16) * 33 + k];
        float4 q0 = Bs[cb * 33 + k], q1 = Bs[(cb + 16) * 33 + k];
        fma4(r0, q0, s00); fma4(r0, q1, s01);
        fma4(r1, q0, s10); fma4(r1, q1, s11);
    }
    __syncthreads();
    float na[2] = { nA[ra], nA[ra + 16] };
    float nb[2] = { nB[cb], nB[cb + 16] };
    float acc[2][2] = { {hsum4(s00), hsum4(s01)}, {hsum4(s10), hsum4(s11)} };
    long ob0 = (long)(t * 2 + 0) * NN * NN;
    long ob1 = (long)(t * 2 + 1) * NN * NN;
#pragma unroll
    for (int k = 0; k < 2; ++k) {
#pragma unroll
        for (int q = 0; q < 2; ++q) {
            int n = nt * 32 + ra + k * 16;
            int m = mt * 32 + cb + q * 16;
            float sim = __fdividef(acc[k][q], na[k] * nb[q] + 1e-6f);
            float v0 = fminf(fmaxf(sim, 0.0f), 1.0f);
            float v1 = fminf(fmaxf(1.0f - sim, 0.0f), 1.0f);
            out[ob0 + n * NN + m] = v0;
            out[ob1 + n * NN + m] = v1;
        }
    }
    if (BN && nt == mt) {
        float4* xo = (float4*)(xout + (t * NN + nt * 32) * FF);
#pragma unroll
        for (int i = 0; i < 4; ++i) {
            int idx = tid + i * 256;
            int r = idx >> 5, k = idx & 31;
            xo[idx] = As[r * 33 + k];
        }
    }
}

// ---- standalone sim_cal (BN path): grid (16 tiles, T), 256 threads ----
__global__ void __launch_bounds__(256) k_simcal(
        const float* __restrict__ src, const float* __restrict__ stats,
        const float* __restrict__ gamma, const float* __restrict__ beta,
        float* __restrict__ xout, float* __restrict__ out) {
    simcal_body<true>(src, stats, gamma, beta, xout, out,
                      blockIdx.y, blockIdx.x, threadIdx.x);
}

// ---- fused: layer-0 edge pass (z<2, 8 i-rows, 64-j half) + e0 fp16 store
//      + input sim_cal (z==2).  grid (16, T, 3), 256 threads
__global__ void __launch_bounds__(256) k_fused0(
        const float* __restrict__ node, const float* __restrict__ edge,
        const float* __restrict__ ew, const float* __restrict__ eb,
        float* __restrict__ stats, float* __restrict__ out) {
    int z = blockIdx.z;
    int tid = threadIdx.x;
    if (z == 2) {
        simcal_body<false>(node, nullptr, nullptr, nullptr, nullptr, out,
                           blockIdx.y, blockIdx.x, tid);
        return;
    }
    if (z == 0 && blockIdx.x == 0 && blockIdx.y == 0)
        stats[tid] = 0.0f;   // 256 threads cover sum0+sumsq0
    int t = blockIdx.y;
    int lane = tid & 31, w = tid >> 5;
    int i = blockIdx.x * 8 + w;
    int j0 = z * 64;
    float w0 = ew[0], w1 = ew[1], w2 = ew[2], b = eb[0];
    const float4* x4 = (const float4*)(node + t * NN * FF);
    float4 xi = x4[i * 32 + lane];
    float cx = fmaf(w0 + w1, xi.x, b), cy = fmaf(w0 + w1, xi.y, b);
    float cz = fmaf(w0 + w1, xi.z, b), cw_ = fmaf(w0 + w1, xi.w, b);
    const float4* e4 = (const float4*)(edge + ((size_t)(t * NN + i) * NN) * FF);
    __half* e0row = g_e0 + ((size_t)(t * NN + i) * NN) * FF;
    float ax = 0.f, ay = 0.f, az = 0.f, aw = 0.f;
#pragma unroll 8
    for (int jj = 0; jj < 64; ++jj) {
        int j = j0 + jj;
        float4 e = __ldcs(&e4[j * 32 + lane]);
        float4 xj = x4[j * 32 + lane];
        float rx = tanh_fast(fmaf(w2, e.x, fmaf(-w1, xj.x, cx)));
        float ry = tanh_fast(fmaf(w2, e.y, fmaf(-w1, xj.y, cy)));
        float rz = tanh_fast(fmaf(w2, e.z, fmaf(-w1, xj.z, cz)));
        float rw = tanh_fast(fmaf(w2, e.w, fmaf(-w1, xj.w, cw_)));
        ax += rx; ay += ry; az += rz; aw += rw;
        __half2 h01 = __floats2half2_rn(rx, ry);
        __half2 h23 = __floats2half2_rn(rz, rw);
        uint2 u;
        u.x = *reinterpret_cast<unsigned*>(&h01);
        u.y = *reinterpret_cast<unsigned*>(&h23);
        *reinterpret_cast<uint2*>(e0row + (size_t)j * FF + lane * 4) = u;
    }
    if ((i >> 6) == z) {   // subtract diagonal if i falls in this half
        float4 eii = e4[i * 32 + lane];
        ax -= tanh_fast(fmaf(w2, eii.x, fmaf(-w1, xi.x, cx)));
        ay -= tanh_fast(fmaf(w2, eii.y, fmaf(-w1, xi.y, cy)));
        az -= tanh_fast(fmaf(w2, eii.z, fmaf(-w1, xi.z, cz)));
        aw -= tanh_fast(fmaf(w2, eii.w, fmaf(-w1, xi.w, cw_)));
    }
    float4 acc; acc.x = ax; acc.y = ay; acc.z = az; acc.w = aw;
    ((float4*)(g_aggr + z * SEG + (t * NN + i) * FF))[lane] = acc;
}

// ---- layer-1: read fp16 e0, f16x2 tanh, partial-aggregate ----
// grid (16, T, 2), 256 threads: 8 i-rows, 64-j half
__global__ void __launch_bounds__(256) k_edge1(
        const float* __restrict__ node1,
        const float* __restrict__ ew, const float* __restrict__ eb,
        float* __restrict__ stats) {
    int z = blockIdx.z;
    int tid = threadIdx.x;
    if (z == 0 && blockIdx.x == 0 && blockIdx.y == 0)
        stats[tid] = 0.0f;
    int t = blockIdx.y;
    int lane = tid & 31, w = tid >> 5;
    int i = blockIdx.x * 8 + w;
    int j0 = z * 64;
    float w10 = ew[3], w11 = ew[4], w12 = ew[5], b1 = eb[1];
    const float4* x14 = (const float4*)(node1 + t * NN * FF);
    float4 xi1 = x14[i * 32 + lane];
    float c1x = fmaf(w10 + w11, xi1.x, b1), c1y = fmaf(w10 + w11, xi1.y, b1);
    float c1z = fmaf(w10 + w11, xi1.z, b1), c1w = fmaf(w10 + w11, xi1.w, b1);
    const __half* e0row = g_e0 + ((size_t)(t * NN + i) * NN) * FF;
    float ax = 0.f, ay = 0.f, az = 0.f, aw = 0.f;
#pragma unroll 8
    for (int jj = 0; jj < 64; ++jj) {
        int j = j0 + jj;
        uint2 u = *reinterpret_cast<const uint2*>(e0row + (size_t)j * FF + lane * 4);
        __half2 h01 = *reinterpret_cast<__half2*>(&u.x);
        __half2 h23 = *reinterpret_cast<__half2*>(&u.y);
        float2 f01 = __half22float2(h01);
        float2 f23 = __half22float2(h23);
        float4 x1 = x14[j * 32 + lane];
        float a0 = fmaf(w12, f01.x, fmaf(-w11, x1.x, c1x));
        float a1 = fmaf(w12, f01.y, fmaf(-w11, x1.y, c1y));
        float a2 = fmaf(w12, f23.x, fmaf(-w11, x1.z, c1z));
        float a3 = fmaf(w12, f23.y, fmaf(-w11, x1.w, c1w));
        float2 r01 = __half22float2(tanh_fast_h2(__floats2half2_rn(a0, a1)));
        float2 r23 = __half22float2(tanh_fast_h2(__floats2half2_rn(a2, a3)));
        ax += r01.x; ay += r01.y; az += r23.x; aw += r23.y;
    }
    if ((i >> 6) == z) {   // subtract diagonal (same stored value as added)
        uint2 u = *reinterpret_cast<const uint2*>(e0row + (size_t)i * FF + lane * 4);
        __half2 h01 = *reinterpret_cast<__half2*>(&u.x);
        __half2 h23 = *reinterpret_cast<__half2*>(&u.y);
        float2 f01 = __half22float2(h01);
        float2 f23 = __half22float2(h23);
        float a0 = fmaf(w12, f01.x, fmaf(-w11, xi1.x, c1x));
        float a1 = fmaf(w12, f01.y, fmaf(-w11, xi1.y, c1y));
        float a2 = fmaf(w12, f23.x, fmaf(-w11, xi1.z, c1z));
        float a3 = fmaf(w12, f23.y, fmaf(-w11, xi1.w, c1w));
        float2 r01 = __half22float2(tanh_fast_h2(__floats2half2_rn(a0, a1)));
        float2 r23 = __half22float2(tanh_fast_h2(__floats2half2_rn(a2, a3)));
        ax -= r01.x; ay -= r01.y; az -= r23.x; aw -= r23.y;
    }
    float4 acc; acc.x = ax; acc.y = ay; acc.z = az; acc.w = aw;
    ((float4*)(g_aggr + z * SEG + (t * NN + i) * FF))[lane] = acc;
}

// ---- node GEMM (all-float4 mainloop) + fused BN-stat accumulation ----
__global__ void __launch_bounds__(256) k_gemm(
        const float* __restrict__ x, const float* __restrict__ cw,
        const float* __restrict__ W, float* __restrict__ y, float* __restrict__ stats) {
    extern __shared__ float4 sm4[];
    float4* Ws = sm4;               // [g][k], pitch 33 float4
    float4* hs = sm4 + 128 * 33;    // [r][k], pitch 33 float4
    float c0 = cw[0], c1 = cw[1];
    int t = blockIdx.x >> 3;
    int r0 = (blockIdx.x & 7) * 16;
    int tid = threadIdx.x;
    const float4* W4 = (const float4*)W;
#pragma unroll
    for (int i = 0; i < 16; ++i) {
        int idx = tid + i * 256;
        int g = idx >> 5, k = idx & 31;
        Ws[g * 33 + k] = W4[idx];
    }
    const float4* x4 = (const float4*)(x + (t * NN + r0) * FF);
    const float4* a4 = (const float4*)(g_aggr + 0 * SEG + (t * NN + r0) * FF);
    const float4* b4 = (const float4*)(g_aggr + 1 * SEG + (t * NN + r0) * FF);
#pragma unroll
    for (int i = 0; i < 2; ++i) {
        int idx = tid + i * 256;
        int r = idx >> 5, k = idx & 31;
        float4 xv = x4[idx], av = a4[idx], bv = b4[idx], h;
        h.x = lrelu(fmaf(c1, av.x + bv.x, c0 * xv.x));
        h.y = lrelu(fmaf(c1, av.y + bv.y, c0 * xv.y));
        h.z = lrelu(fmaf(c1, av.z + bv.z, c0 * xv.z));
        h.w = lrelu(fmaf(c1, av.w + bv.w, c0 * xv.w));
        hs[r * 33 + k] = h;
    }
    __syncthreads();
    int rt = tid & 7, gt = tid >> 3;
    float acc[2][4] = { {0.f,0.f,0.f,0.f}, {0.f,0.f,0.f,0.f} };
#pragma unroll 4
    for (int k = 0; k < 32; ++k) {
        float4 a0 = hs[rt * 33 + k];
        float4 a1 = hs[(rt + 8) * 33 + k];
#pragma unroll
        for (int q = 0; q < 4; ++q) {
            float4 wv = Ws[(gt * 4 + q) * 33 + k];
            acc[0][q] = fmaf(a0.x, wv.x, fmaf(a0.y, wv.y, fmaf(a0.z, wv.z, fmaf(a0.w, wv.w, acc[0][q]))));
            acc[1][q] = fmaf(a1.x, wv.x, fmaf(a1.y, wv.y, fmaf(a1.z, wv.z, fmaf(a1.w, wv.w, acc[1][q]))));
        }
    }
    float4 v0; v0.x = acc[0][0]; v0.y = acc[0][1]; v0.z = acc[0][2]; v0.w = acc[0][3];
    float4 v1; v1.x = acc[1][0]; v1.y = acc[1][1]; v1.z = acc[1][2]; v1.w = acc[1][3];
    *(float4*)(y + (t * NN + r0 + rt) * FF + gt * 4) = v0;
    *(float4*)(y + (t * NN + r0 + rt + 8) * FF + gt * 4) = v1;
#pragma unroll
    for (int q = 0; q < 4; ++q) {
        float s  = acc[0][q] + acc[1][q];
        float ss = fmaf(acc[0][q], acc[0][q], acc[1][q] * acc[1][q]);
#pragma unroll
        for (int o = 4; o; o >>= 1) {
            s  += __shfl_down_sync(0xffffffffu, s,  o, 8);
            ss += __shfl_down_sync(0xffffffffu, ss, o, 8);
        }
        if (rt == 0) {
            int g = gt * 4 + q;
            atomicAdd(&stats[g], s);
            atomicAdd(&stats[FF + g], ss);
        }
    }
}

extern "C" void kernel_launch(void* const* d_in, const int* in_sizes, int n_in,
                              void* d_out, int out_size) {
    const float* node  = (const float*)d_in[0];
    const float* edge  = (const float*)d_in[1];
    const float* ew    = (const float*)d_in[2];   // [L,3]
    const float* ebv   = (const float*)d_in[3];   // [L]
    const float* cw    = (const float*)d_in[4];   // [L,2]
    const float* nw    = (const float*)d_in[5];   // [L,F,F]
    const float* gamma = (const float*)d_in[6];   // [L,F]
    const float* beta  = (const float*)d_in[7];   // [L,F]
    float* out = (float*)d_out;

    void *p1, *p2, *py, *ps;
    cudaGetSymbolAddress(&p1, g_node1);
    cudaGetSymbolAddress(&p2, g_node2);
    cudaGetSymbolAddress(&py, g_y);
    cudaGetSymbolAddress(&ps, g_stats);
    float* node1 = (float*)p1;
    float* node2 = (float*)p2;
    float* y     = (float*)py;
    float* st    = (float*)ps;

    size_t gemm_smem = (size_t)(128 * 33 + 16 * 33) * sizeof(float4);
    cudaFuncSetAttribute(k_gemm, cudaFuncAttributeMaxDynamicSharedMemorySize, (int)gemm_smem);

    const int OUTBLK = TT * 2 * NN * NN;

    // ---- layer 0 (input sim_cal fused as z==2; e0 stored fp16) ----
    k_fused0<<<dim3(16, TT, 3), 256>>>(node, edge, ew, ebv, st, out);
    k_gemm<<<TT * 8, 256, gemm_smem>>>(node, cw, nw, y, st);
    k_simcal<<<dim3(16, TT), 256>>>(y, st, gamma, beta, node1, out + OUTBLK);

    // ---- layer 1 (reads fp16 e0; f16x2 tanh) ----
    k_edge1<<<dim3(16, TT, 2), 256>>>(node1, ew, ebv, st + 2 * FF);
    k_gemm<<<TT * 8, 256, gemm_smem>>>(node1, cw + 2, nw + FF * FF, y, st + 2 * FF);
    k_simcal<<<dim3(16, TT), 256>>>(y, st + 2 * FF, gamma + FF, beta + FF, node2,
                                    out + 2 * OUTBLK);
}